// round 2
// baseline (speedup 1.0000x reference)
#include <cuda_runtime.h>
#include <math.h>

// Problem constants
#define BB 2
#define SS 2048
#define DD 1024
#define HH 16
#define HD 64
#define BH (BB*HH)          // 32
#define MROWS (BB*SS)       // 4096

// Scratch (static device globals: allocation-free)
__device__ float g_q[BB*HH*SS*HD];
__device__ float g_k[BB*HH*SS*HD];
__device__ float g_v[BB*HH*SS*HD];
__device__ float g_attn[MROWS*DD];

// ---------------------------------------------------------------------------
// SGEMM: C[M,N] = A[M,K] @ B[K,N] + bias[N]
// BM=128, BN=128, BK=16, 256 threads, 8x8 per thread.
// EPI=0: scatter into g_q/g_k/g_v with head-major layout (Q scaled by 0.125)
// EPI=1: plain store to C
// ---------------------------------------------------------------------------
template<int EPI>
__global__ __launch_bounds__(256)
void sgemm_kernel(const float* __restrict__ A, const float* __restrict__ Bm,
                  const float* __restrict__ bias, float* __restrict__ C,
                  int M, int N, int K)
{
    __shared__ float As[16][128];
    __shared__ float Bs[16][128];

    const int tid = threadIdx.x;
    const int tx  = tid & 15;       // 0..15  -> N direction
    const int ty  = tid >> 4;       // 0..15  -> M direction
    const int brow = blockIdx.y;
    const int bcol = blockIdx.x;

    const float* Ab = A + (size_t)brow * 128 * K;
    const float* Bb = Bm + (size_t)bcol * 128;

    float acc[8][8];
    #pragma unroll
    for (int i = 0; i < 8; i++)
        #pragma unroll
        for (int j = 0; j < 8; j++) acc[i][j] = 0.0f;

    const int a_r = tid >> 2;        // 0..63
    const int a_c = (tid & 3) * 4;   // 0,4,8,12
    const int b_r = tid >> 5;        // 0..7
    const int b_c = (tid & 31) * 4;  // 0..124

    for (int k0 = 0; k0 < K; k0 += 16) {
        __syncthreads();   // protect previous iteration's reads
        #pragma unroll
        for (int p = 0; p < 2; p++) {
            int r = p * 64 + a_r;
            float4 t = *reinterpret_cast<const float4*>(&Ab[(size_t)r * K + k0 + a_c]);
            As[a_c + 0][r] = t.x;
            As[a_c + 1][r] = t.y;
            As[a_c + 2][r] = t.z;
            As[a_c + 3][r] = t.w;
        }
        #pragma unroll
        for (int p = 0; p < 2; p++) {
            int r = p * 8 + b_r;
            float4 t = *reinterpret_cast<const float4*>(&Bb[(size_t)(k0 + r) * N + b_c]);
            *reinterpret_cast<float4*>(&Bs[r][b_c]) = t;
        }
        __syncthreads();

        #pragma unroll
        for (int kk = 0; kk < 16; kk++) {
            float ar[8], br[8];
            *reinterpret_cast<float4*>(&ar[0]) = *reinterpret_cast<float4*>(&As[kk][ty * 8]);
            *reinterpret_cast<float4*>(&ar[4]) = *reinterpret_cast<float4*>(&As[kk][ty * 8 + 4]);
            *reinterpret_cast<float4*>(&br[0]) = *reinterpret_cast<float4*>(&Bs[kk][tx * 8]);
            *reinterpret_cast<float4*>(&br[4]) = *reinterpret_cast<float4*>(&Bs[kk][tx * 8 + 4]);
            #pragma unroll
            for (int i = 0; i < 8; i++)
                #pragma unroll
                for (int j = 0; j < 8; j++)
                    acc[i][j] = fmaf(ar[i], br[j], acc[i][j]);
        }
    }

    if (EPI == 0) {
        // QKV scatter. Each block's 128 output cols lie entirely within one
        // of {Q,K,V} since 1024 % 128 == 0.
        const int part = (bcol * 128) >> 10;        // 0=Q, 1=K, 2=V
        float* dst = (part == 0) ? g_q : ((part == 1) ? g_k : g_v);
        const float scale = (part == 0) ? 0.125f : 1.0f;   // 1/sqrt(64) folded into Q
        #pragma unroll
        for (int i = 0; i < 8; i++) {
            int m = brow * 128 + ty * 8 + i;
            int b = m >> 11;            // /2048
            int s = m & 2047;
            #pragma unroll
            for (int j = 0; j < 8; j++) {
                int n = bcol * 128 + tx * 8 + j;
                float v = (acc[i][j] + __ldg(&bias[n])) * scale;
                int col = n & 1023;
                int h = col >> 6;
                int d = col & 63;
                dst[(((size_t)(b * 16 + h) * 2048) + s) * 64 + d] = v;
            }
        }
    } else {
        #pragma unroll
        for (int i = 0; i < 8; i++) {
            int m = brow * 128 + ty * 8 + i;
            #pragma unroll
            for (int j = 0; j < 8; j++) {
                int n = bcol * 128 + tx * 8 + j;
                C[(size_t)m * N + n] = acc[i][j] + __ldg(&bias[n]);
            }
        }
    }
}

// ---------------------------------------------------------------------------
// Flash attention, fp32, causal.
// grid = (S/64 q-tiles, B*H). 256 threads as 16x16, 4x4 per thread.
// Static smem exactly 48KB: Qs(pitch 64) + KP rotated-swizzle buffer + Vs(pitch 64).
// KP swizzle: element (c, d) lives at KPs[c*64 + ((d + c) & 63)]  -> <=2-way conflicts.
// Online softmax with shfl row-reductions over 16-lane segments.
// ---------------------------------------------------------------------------
__global__ __launch_bounds__(256)
void flash_kernel()
{
    __shared__ float Qs [64 * 64];   // Qs[r*64 + d]
    __shared__ float KPs[64 * 64];   // K tile / P tile, rotation swizzled
    __shared__ float Vs [64 * 64];   // Vs[j*64 + d]

    const int bh = blockIdx.y;       // 0..31  (b*16 + h)
    const int qt = blockIdx.x;       // 0..31
    const int tid = threadIdx.x;
    const int tx = tid & 15;
    const int ty = tid >> 4;

    // Load Q tile (64 rows x 64 floats, contiguous)
    {
        const float* qb = g_q + ((size_t)bh * SS + qt * 64) * HD;
        #pragma unroll
        for (int p = 0; p < 4; p++) {
            int idx = p * 256 + tid;
            int r = idx >> 4;
            int c = (idx & 15) * 4;
            float4 t = *reinterpret_cast<const float4*>(&qb[r * 64 + c]);
            *reinterpret_cast<float4*>(&Qs[r * 64 + c]) = t;
        }
    }

    float m_i[4], l_i[4], o_acc[4][4];
    #pragma unroll
    for (int i = 0; i < 4; i++) {
        m_i[i] = -1e30f;
        l_i[i] = 0.0f;
        #pragma unroll
        for (int j = 0; j < 4; j++) o_acc[i][j] = 0.0f;
    }

    for (int kt = 0; kt <= qt; kt++) {
        __syncthreads();   // previous tile's P/V reads done (also covers Q load on iter 0)

        // Load K and V tiles (K swizzled: row c, col d -> KPs[c*64 + ((d+c)&63)])
        {
            const float* kb = g_k + ((size_t)bh * SS + kt * 64) * HD;
            const float* vb = g_v + ((size_t)bh * SS + kt * 64) * HD;
            #pragma unroll
            for (int p = 0; p < 4; p++) {
                int idx = p * 256 + tid;
                int r = idx >> 4;
                int c = (idx & 15) * 4;
                float4 t = *reinterpret_cast<const float4*>(&kb[r * 64 + c]);
                KPs[r * 64 + ((c + 0 + r) & 63)] = t.x;
                KPs[r * 64 + ((c + 1 + r) & 63)] = t.y;
                KPs[r * 64 + ((c + 2 + r) & 63)] = t.z;
                KPs[r * 64 + ((c + 3 + r) & 63)] = t.w;
                float4 u = *reinterpret_cast<const float4*>(&vb[r * 64 + c]);
                *reinterpret_cast<float4*>(&Vs[r * 64 + c]) = u;
            }
        }
        __syncthreads();

        // Scores: s[i][j] = sum_d Q[r][d] * K[c][d]   (scale already in Q)
        float s[4][4];
        #pragma unroll
        for (int i = 0; i < 4; i++)
            #pragma unroll
            for (int j = 0; j < 4; j++) s[i][j] = 0.0f;

        #pragma unroll 8
        for (int d = 0; d < 64; d++) {
            float qr[4], kr[4];
            #pragma unroll
            for (int i = 0; i < 4; i++) qr[i] = Qs[(ty * 4 + i) * 64 + d];
            #pragma unroll
            for (int j = 0; j < 4; j++) {
                int c = tx * 4 + j;
                kr[j] = KPs[c * 64 + ((d + c) & 63)];
            }
            #pragma unroll
            for (int i = 0; i < 4; i++)
                #pragma unroll
                for (int j = 0; j < 4; j++)
                    s[i][j] = fmaf(qr[i], kr[j], s[i][j]);
        }

        // Causal mask on the diagonal tile
        if (kt == qt) {
            #pragma unroll
            for (int i = 0; i < 4; i++)
                #pragma unroll
                for (int j = 0; j < 4; j++)
                    if (tx * 4 + j > ty * 4 + i) s[i][j] = -1e30f;
        }

        __syncthreads();   // all K reads done before P overwrites KPs

        // Online softmax update + write P into KPs (P(row,col) at [row*64 + ((col+row)&63)])
        #pragma unroll
        for (int i = 0; i < 4; i++) {
            float tm = fmaxf(fmaxf(s[i][0], s[i][1]), fmaxf(s[i][2], s[i][3]));
            #pragma unroll
            for (int off = 8; off > 0; off >>= 1)
                tm = fmaxf(tm, __shfl_xor_sync(0xffffffffu, tm, off, 16));
            float mnew = fmaxf(m_i[i], tm);
            float corr = __expf(m_i[i] - mnew);
            float rs = 0.0f;
            int row = ty * 4 + i;
            #pragma unroll
            for (int j = 0; j < 4; j++) {
                float pv = __expf(s[i][j] - mnew);
                int col = tx * 4 + j;
                KPs[row * 64 + ((col + row) & 63)] = pv;
                rs += pv;
            }
            #pragma unroll
            for (int off = 8; off > 0; off >>= 1)
                rs += __shfl_xor_sync(0xffffffffu, rs, off, 16);
            l_i[i] = l_i[i] * corr + rs;
            m_i[i] = mnew;
            #pragma unroll
            for (int j = 0; j < 4; j++) o_acc[i][j] *= corr;
        }
        __syncthreads();

        // O += P @ V
        #pragma unroll 8
        for (int jj = 0; jj < 64; jj++) {
            float pr[4], vr[4];
            #pragma unroll
            for (int i = 0; i < 4; i++) {
                int row = ty * 4 + i;
                pr[i] = KPs[row * 64 + ((jj + row) & 63)];
            }
            *reinterpret_cast<float4*>(&vr[0]) =
                *reinterpret_cast<float4*>(&Vs[jj * 64 + tx * 4]);
            #pragma unroll
            for (int i = 0; i < 4; i++)
                #pragma unroll
                for (int j = 0; j < 4; j++)
                    o_acc[i][j] = fmaf(pr[i], vr[j], o_acc[i][j]);
        }
    }

    // Write merged-head layout: g_attn[(b*S + s)*D + h*64 + d]
    const int b = bh >> 4;
    const int h = bh & 15;
    #pragma unroll
    for (int i = 0; i < 4; i++) {
        float inv = 1.0f / l_i[i];
        int grow = qt * 64 + ty * 4 + i;
        size_t base = ((size_t)(b * SS + grow)) * DD + h * 64 + tx * 4;
        #pragma unroll
        for (int j = 0; j < 4; j++)
            g_attn[base + j] = o_acc[i][j] * inv;
    }
}

// ---------------------------------------------------------------------------
extern "C" void kernel_launch(void* const* d_in, const int* in_sizes, int n_in,
                              void* d_out, int out_size)
{
    (void)in_sizes; (void)n_in; (void)out_size;
    const float* x   = (const float*)d_in[0];  // [B,S,D]
    const float* w1  = (const float*)d_in[1];  // [D, 3D]
    const float* b1  = (const float*)d_in[2];  // [3D]
    const float* w2  = (const float*)d_in[3];  // [D, D]
    const float* b2  = (const float*)d_in[4];  // [D]
    float* out = (float*)d_out;                // [B,S,D]

    // 1) QKV = X @ W1 + b1, scattered into head-major Q/K/V (Q pre-scaled)
    sgemm_kernel<0><<<dim3(3 * DD / 128, MROWS / 128), 256>>>(
        x, w1, b1, nullptr, MROWS, 3 * DD, DD);

    // 2) causal flash attention -> g_attn [B,S,D]
    flash_kernel<<<dim3(SS / 64, BH), 256>>>();

    // 3) out = attn @ W2 + b2
    void* attn_ptr = nullptr;
    cudaGetSymbolAddress(&attn_ptr, g_attn);
    sgemm_kernel<1><<<dim3(DD / 128, MROWS / 128), 256>>>(
        (const float*)attn_ptr, w2, b2, out, MROWS, DD, DD);
}

// round 4
// speedup vs baseline: 1.3818x; 1.3818x over previous
#include <cuda_runtime.h>
#include <cuda_bf16.h>
#include <cstdint>
#include <math.h>

// Problem constants
#define BB 2
#define SS 2048
#define DD 1024
#define HH 16
#define HD 64
#define BH (BB*HH)          // 32
#define MROWS (BB*SS)       // 4096

// ---------------------------------------------------------------------------
// Scratch (static device globals: allocation-free)
// ---------------------------------------------------------------------------
__device__ float g_q[BB*HH*SS*HD];
__device__ float g_k[BB*HH*SS*HD];
__device__ float g_v[BB*HH*SS*HD];
__device__ __nv_bfloat16 g_xh [MROWS*DD];
__device__ __nv_bfloat16 g_xl [MROWS*DD];
__device__ __nv_bfloat16 g_w1ht[3*DD*DD];   // W1^T split hi  [3072,1024]
__device__ __nv_bfloat16 g_w1lt[3*DD*DD];
__device__ __nv_bfloat16 g_w2ht[DD*DD];     // W2^T split hi  [1024,1024]
__device__ __nv_bfloat16 g_w2lt[DD*DD];
__device__ __nv_bfloat16 g_ah [MROWS*DD];   // attention output split
__device__ __nv_bfloat16 g_al [MROWS*DD];

// ---------------------------------------------------------------------------
// PTX helpers (sm_80-portable only: mma.sync / ldmatrix / cp.async)
// ---------------------------------------------------------------------------
__device__ __forceinline__ uint32_t smem_to_u32(const void* p) {
    uint32_t a;
    asm("{ .reg .u64 t; cvta.to.shared.u64 t, %1; cvt.u32.u64 %0, t; }"
        : "=r"(a) : "l"(p));
    return a;
}
__device__ __forceinline__ void ldsm_x4(uint32_t* r, uint32_t addr) {
    asm volatile("ldmatrix.sync.aligned.m8n8.x4.shared.b16 {%0,%1,%2,%3}, [%4];"
                 : "=r"(r[0]), "=r"(r[1]), "=r"(r[2]), "=r"(r[3]) : "r"(addr));
}
__device__ __forceinline__ void mma_bf16(float* c, const uint32_t* a, uint32_t b0, uint32_t b1) {
    asm volatile(
        "mma.sync.aligned.m16n8k16.row.col.f32.bf16.bf16.f32 "
        "{%0,%1,%2,%3}, {%4,%5,%6,%7}, {%8,%9}, {%0,%1,%2,%3};"
        : "+f"(c[0]), "+f"(c[1]), "+f"(c[2]), "+f"(c[3])
        : "r"(a[0]), "r"(a[1]), "r"(a[2]), "r"(a[3]), "r"(b0), "r"(b1));
}
__device__ __forceinline__ void cp_async16(uint32_t saddr, const void* gptr) {
    asm volatile("cp.async.cg.shared.global [%0], [%1], 16;" :: "r"(saddr), "l"(gptr));
}
#define CP_COMMIT()  asm volatile("cp.async.commit_group;" ::: "memory")
#define CP_WAIT(n)   asm volatile("cp.async.wait_group %0;" :: "n"(n) : "memory")

// ---------------------------------------------------------------------------
// Conversion kernels
// ---------------------------------------------------------------------------
__global__ __launch_bounds__(256)
void split_kernel(const float* __restrict__ x, __nv_bfloat16* __restrict__ xh,
                  __nv_bfloat16* __restrict__ xl)
{
    int i = (blockIdx.x * 256 + threadIdx.x) * 4;
    float4 v = *reinterpret_cast<const float4*>(x + i);
    float a[4] = {v.x, v.y, v.z, v.w};
    #pragma unroll
    for (int j = 0; j < 4; j++) {
        __nv_bfloat16 h = __float2bfloat16(a[j]);
        xh[i + j] = h;
        xl[i + j] = __float2bfloat16(a[j] - __bfloat162float(h));
    }
}

// W[K,N] fp32 -> WT hi/lo bf16 [N,K]
__global__ __launch_bounds__(256)
void tsplit_kernel(const float* __restrict__ W, __nv_bfloat16* __restrict__ WTh,
                   __nv_bfloat16* __restrict__ WTl, int K, int N)
{
    __shared__ float t[32][33];
    const int k0 = blockIdx.y * 32, n0 = blockIdx.x * 32;
    const int tx = threadIdx.x & 31, ty = threadIdx.x >> 5;  // 32 x 8
    #pragma unroll
    for (int i = 0; i < 4; i++)
        t[ty + i * 8][tx] = W[(size_t)(k0 + ty + i * 8) * N + n0 + tx];
    __syncthreads();
    #pragma unroll
    for (int i = 0; i < 4; i++) {
        int n = ty + i * 8;
        float v = t[tx][n];
        __nv_bfloat16 h = __float2bfloat16(v);
        WTh[(size_t)(n0 + n) * K + k0 + tx] = h;
        WTl[(size_t)(n0 + n) * K + k0 + tx] = __float2bfloat16(v - __bfloat162float(h));
    }
}

// ---------------------------------------------------------------------------
// mma.sync GEMM: D[M,N] = (Ah+Al)[M,K] @ (Bh+Bl)[N,K]^T + bias (bf16-split)
// BM=BN=128, BK=32, 256 threads (8 warps, 2x4), warp tile 64x32.
// SMEM tiles [128 x 32 bf16] at 80B pitch; cp.async double buffer.
// EPI=0: scatter into g_q/g_k/g_v (Q scaled). EPI=1: plain store to C.
// ---------------------------------------------------------------------------
#define TILE_B  10240           // 128 * 80
#define STAGE_B 40960           // 4 tiles

template<int EPI>
__global__ __launch_bounds__(256, 1)
void mma_gemm(const __nv_bfloat16* __restrict__ Ah, const __nv_bfloat16* __restrict__ Al,
              const __nv_bfloat16* __restrict__ Bh, const __nv_bfloat16* __restrict__ Bl,
              const float* __restrict__ bias, float* __restrict__ C,
              int N, int K)
{
    extern __shared__ char dsm[];
    const uint32_t sb = smem_to_u32(dsm);

    const int tid = threadIdx.x;
    const int wid = tid >> 5;
    const int lane = tid & 31;
    const int bm = blockIdx.y;
    const int bn = blockIdx.x;
    const int wm = wid & 1;       // 0..1 (M)
    const int wn = wid >> 1;      // 0..3 (N)

    const __nv_bfloat16* gsrc[4];
    gsrc[0] = Ah + (size_t)bm * 128 * K;
    gsrc[1] = Al + (size_t)bm * 128 * K;
    gsrc[2] = Bh + (size_t)bn * 128 * K;
    gsrc[3] = Bl + (size_t)bn * 128 * K;

    // loader mapping: 512 16B-chunks per tile, thread does 2
    const int l_row0 = tid >> 2;          // chunk = tid   -> row tid/4
    const int l_c16  = tid & 3;           // 16B col index

    auto load_stage = [&](int stage, int k0) {
        uint32_t sdst = sb + stage * STAGE_B;
        #pragma unroll
        for (int op = 0; op < 4; op++) {
            const __nv_bfloat16* g = gsrc[op];
            #pragma unroll
            for (int h = 0; h < 2; h++) {
                int row = l_row0 + h * 64;
                cp_async16(sdst + op * TILE_B + row * 80 + l_c16 * 16,
                           g + (size_t)row * K + k0 + l_c16 * 8);
            }
        }
    };

    float acc[4][4][4];
    #pragma unroll
    for (int mt = 0; mt < 4; mt++)
        #pragma unroll
        for (int nt = 0; nt < 4; nt++)
            #pragma unroll
            for (int r = 0; r < 4; r++) acc[mt][nt][r] = 0.0f;

    const int NCH = K >> 5;    // K/32

    load_stage(0, 0);
    CP_COMMIT();

    for (int c = 0; c < NCH; c++) {
        const int stage = c & 1;
        if (c + 1 < NCH) {
            load_stage((c + 1) & 1, (c + 1) * 32);
            CP_COMMIT();
            CP_WAIT(1);
        } else {
            CP_WAIT(0);
        }
        __syncthreads();

        const uint32_t sA_h = sb + stage * STAGE_B + 0 * TILE_B;
        const uint32_t sA_l = sb + stage * STAGE_B + 1 * TILE_B;
        const uint32_t sB_h = sb + stage * STAGE_B + 2 * TILE_B;
        const uint32_t sB_l = sb + stage * STAGE_B + 3 * TILE_B;

        #pragma unroll
        for (int ks = 0; ks < 2; ks++) {
            const int kbyte = ks * 32;
            uint32_t ah[4][4], al[4][4], bh[2][4], bl[2][4];

            #pragma unroll
            for (int mt = 0; mt < 4; mt++) {
                uint32_t roff = (uint32_t)(wm * 64 + mt * 16 + (lane & 15)) * 80
                              + (uint32_t)(lane >> 4) * 16 + kbyte;
                ldsm_x4(ah[mt], sA_h + roff);
                ldsm_x4(al[mt], sA_l + roff);
            }
            #pragma unroll
            for (int nt2 = 0; nt2 < 2; nt2++) {
                int g = lane >> 3;                       // 0..3
                uint32_t roff = (uint32_t)(wn * 32 + nt2 * 16 + (lane & 7) + ((g >> 1) << 3)) * 80
                              + (uint32_t)(g & 1) * 16 + kbyte;
                ldsm_x4(bh[nt2], sB_h + roff);
                ldsm_x4(bl[nt2], sB_l + roff);
            }

            #pragma unroll
            for (int mt = 0; mt < 4; mt++)
                #pragma unroll
                for (int nt = 0; nt < 4; nt++) {
                    const int nt2 = nt >> 1;
                    const int sel = (nt & 1) * 2;
                    mma_bf16(acc[mt][nt], ah[mt], bh[nt2][sel], bh[nt2][sel + 1]);
                    mma_bf16(acc[mt][nt], ah[mt], bl[nt2][sel], bl[nt2][sel + 1]);
                    mma_bf16(acc[mt][nt], al[mt], bh[nt2][sel], bh[nt2][sel + 1]);
                }
        }
        __syncthreads();
    }

    // Epilogue. acc reg r: row += (r>=2)*8, col += (r&1)
    #pragma unroll
    for (int mt = 0; mt < 4; mt++) {
        #pragma unroll
        for (int nt = 0; nt < 4; nt++) {
            #pragma unroll
            for (int r = 0; r < 4; r++) {
                int m = bm * 128 + wm * 64 + mt * 16 + (lane >> 2) + (r >> 1) * 8;
                int n = bn * 128 + wn * 32 + nt * 8 + (lane & 3) * 2 + (r & 1);
                float v = acc[mt][nt][r] + __ldg(&bias[n]);
                if (EPI == 0) {
                    int part = n >> 10;                  // 0=Q 1=K 2=V
                    float* dst = (part == 0) ? g_q : ((part == 1) ? g_k : g_v);
                    if (part == 0) v *= 0.125f;          // 1/sqrt(64)
                    int b = m >> 11;
                    int s = m & 2047;
                    int col = n & 1023;
                    int hh = col >> 6;
                    int d = col & 63;
                    dst[(((size_t)(b * 16 + hh) * 2048) + s) * 64 + d] = v;
                } else {
                    C[(size_t)m * N + n] = v;
                }
            }
        }
    }
}

// ---------------------------------------------------------------------------
// Flash attention, fp32, causal (unchanged; bf16-split epilogue).
// ---------------------------------------------------------------------------
__global__ __launch_bounds__(256)
void flash_kernel()
{
    __shared__ float Qs [64 * 64];
    __shared__ float KPs[64 * 64];   // K / P, rotation swizzled: (c,d) -> [c*64 + ((d+c)&63)]
    __shared__ float Vs [64 * 64];

    const int bh = blockIdx.y;
    const int qt = blockIdx.x;
    const int tid = threadIdx.x;
    const int tx = tid & 15;
    const int ty = tid >> 4;

    {
        const float* qb = g_q + ((size_t)bh * SS + qt * 64) * HD;
        #pragma unroll
        for (int p = 0; p < 4; p++) {
            int idx = p * 256 + tid;
            int r = idx >> 4;
            int c = (idx & 15) * 4;
            float4 t = *reinterpret_cast<const float4*>(&qb[r * 64 + c]);
            *reinterpret_cast<float4*>(&Qs[r * 64 + c]) = t;
        }
    }

    float m_i[4], l_i[4], o_acc[4][4];
    #pragma unroll
    for (int i = 0; i < 4; i++) {
        m_i[i] = -1e30f;
        l_i[i] = 0.0f;
        #pragma unroll
        for (int j = 0; j < 4; j++) o_acc[i][j] = 0.0f;
    }

    for (int kt = 0; kt <= qt; kt++) {
        __syncthreads();
        {
            const float* kb = g_k + ((size_t)bh * SS + kt * 64) * HD;
            const float* vb = g_v + ((size_t)bh * SS + kt * 64) * HD;
            #pragma unroll
            for (int p = 0; p < 4; p++) {
                int idx = p * 256 + tid;
                int r = idx >> 4;
                int c = (idx & 15) * 4;
                float4 t = *reinterpret_cast<const float4*>(&kb[r * 64 + c]);
                KPs[r * 64 + ((c + 0 + r) & 63)] = t.x;
                KPs[r * 64 + ((c + 1 + r) & 63)] = t.y;
                KPs[r * 64 + ((c + 2 + r) & 63)] = t.z;
                KPs[r * 64 + ((c + 3 + r) & 63)] = t.w;
                float4 u = *reinterpret_cast<const float4*>(&vb[r * 64 + c]);
                *reinterpret_cast<float4*>(&Vs[r * 64 + c]) = u;
            }
        }
        __syncthreads();

        float s[4][4];
        #pragma unroll
        for (int i = 0; i < 4; i++)
            #pragma unroll
            for (int j = 0; j < 4; j++) s[i][j] = 0.0f;

        #pragma unroll 8
        for (int d = 0; d < 64; d++) {
            float qr[4], kr[4];
            #pragma unroll
            for (int i = 0; i < 4; i++) qr[i] = Qs[(ty * 4 + i) * 64 + d];
            #pragma unroll
            for (int j = 0; j < 4; j++) {
                int c = tx * 4 + j;
                kr[j] = KPs[c * 64 + ((d + c) & 63)];
            }
            #pragma unroll
            for (int i = 0; i < 4; i++)
                #pragma unroll
                for (int j = 0; j < 4; j++)
                    s[i][j] = fmaf(qr[i], kr[j], s[i][j]);
        }

        if (kt == qt) {
            #pragma unroll
            for (int i = 0; i < 4; i++)
                #pragma unroll
                for (int j = 0; j < 4; j++)
                    if (tx * 4 + j > ty * 4 + i) s[i][j] = -1e30f;
        }

        __syncthreads();

        #pragma unroll
        for (int i = 0; i < 4; i++) {
            float tm = fmaxf(fmaxf(s[i][0], s[i][1]), fmaxf(s[i][2], s[i][3]));
            #pragma unroll
            for (int off = 8; off > 0; off >>= 1)
                tm = fmaxf(tm, __shfl_xor_sync(0xffffffffu, tm, off, 16));
            float mnew = fmaxf(m_i[i], tm);
            float corr = __expf(m_i[i] - mnew);
            float rs = 0.0f;
            int row = ty * 4 + i;
            #pragma unroll
            for (int j = 0; j < 4; j++) {
                float pv = __expf(s[i][j] - mnew);
                int col = tx * 4 + j;
                KPs[row * 64 + ((col + row) & 63)] = pv;
                rs += pv;
            }
            #pragma unroll
            for (int off = 8; off > 0; off >>= 1)
                rs += __shfl_xor_sync(0xffffffffu, rs, off, 16);
            l_i[i] = l_i[i] * corr + rs;
            m_i[i] = mnew;
            #pragma unroll
            for (int j = 0; j < 4; j++) o_acc[i][j] *= corr;
        }
        __syncthreads();

        #pragma unroll 8
        for (int jj = 0; jj < 64; jj++) {
            float pr[4], vr[4];
            #pragma unroll
            for (int i = 0; i < 4; i++) {
                int row = ty * 4 + i;
                pr[i] = KPs[row * 64 + ((jj + row) & 63)];
            }
            *reinterpret_cast<float4*>(&vr[0]) =
                *reinterpret_cast<float4*>(&Vs[jj * 64 + tx * 4]);
            #pragma unroll
            for (int i = 0; i < 4; i++)
                #pragma unroll
                for (int j = 0; j < 4; j++)
                    o_acc[i][j] = fmaf(pr[i], vr[j], o_acc[i][j]);
        }
    }

    // Write bf16 hi/lo split, merged-head layout
    const int b = bh >> 4;
    const int h = bh & 15;
    #pragma unroll
    for (int i = 0; i < 4; i++) {
        float inv = 1.0f / l_i[i];
        int grow = qt * 64 + ty * 4 + i;
        size_t base = ((size_t)(b * SS + grow)) * DD + h * 64 + tx * 4;
        #pragma unroll
        for (int j = 0; j < 4; j++) {
            float o = o_acc[i][j] * inv;
            __nv_bfloat16 hi = __float2bfloat16(o);
            g_ah[base + j] = hi;
            g_al[base + j] = __float2bfloat16(o - __bfloat162float(hi));
        }
    }
}

// ---------------------------------------------------------------------------
extern "C" void kernel_launch(void* const* d_in, const int* in_sizes, int n_in,
                              void* d_out, int out_size)
{
    (void)in_sizes; (void)n_in; (void)out_size;
    const float* x   = (const float*)d_in[0];  // [B,S,D]
    const float* w1  = (const float*)d_in[1];  // [D, 3D]
    const float* b1  = (const float*)d_in[2];  // [3D]
    const float* w2  = (const float*)d_in[3];  // [D, D]
    const float* b2  = (const float*)d_in[4];  // [D]
    float* out = (float*)d_out;                // [B,S,D]

    const int SMEM_DYN = 2 * STAGE_B;          // 81920
    cudaFuncSetAttribute(mma_gemm<0>, cudaFuncAttributeMaxDynamicSharedMemorySize, SMEM_DYN);
    cudaFuncSetAttribute(mma_gemm<1>, cudaFuncAttributeMaxDynamicSharedMemorySize, SMEM_DYN);

    void *p_xh, *p_xl, *p_w1ht, *p_w1lt, *p_w2ht, *p_w2lt, *p_ah, *p_al;
    cudaGetSymbolAddress(&p_xh, g_xh);     cudaGetSymbolAddress(&p_xl, g_xl);
    cudaGetSymbolAddress(&p_w1ht, g_w1ht); cudaGetSymbolAddress(&p_w1lt, g_w1lt);
    cudaGetSymbolAddress(&p_w2ht, g_w2ht); cudaGetSymbolAddress(&p_w2lt, g_w2lt);
    cudaGetSymbolAddress(&p_ah, g_ah);     cudaGetSymbolAddress(&p_al, g_al);

    // 1) Split X; transpose+split W1, W2
    split_kernel<<<MROWS * DD / 1024, 256>>>(x, (__nv_bfloat16*)p_xh, (__nv_bfloat16*)p_xl);
    tsplit_kernel<<<dim3(3 * DD / 32, DD / 32), 256>>>(w1, (__nv_bfloat16*)p_w1ht,
                                                       (__nv_bfloat16*)p_w1lt, DD, 3 * DD);
    tsplit_kernel<<<dim3(DD / 32, DD / 32), 256>>>(w2, (__nv_bfloat16*)p_w2ht,
                                                   (__nv_bfloat16*)p_w2lt, DD, DD);

    // 2) QKV = X @ W1 + b1 (tensor cores), scattered into head-major Q/K/V
    mma_gemm<0><<<dim3(3 * DD / 128, MROWS / 128), 256, SMEM_DYN>>>(
        (const __nv_bfloat16*)p_xh, (const __nv_bfloat16*)p_xl,
        (const __nv_bfloat16*)p_w1ht, (const __nv_bfloat16*)p_w1lt,
        b1, nullptr, 3 * DD, DD);

    // 3) causal flash attention -> g_ah/g_al (bf16 split)
    flash_kernel<<<dim3(SS / 64, BH), 256>>>();

    // 4) out = attn @ W2 + b2 (tensor cores)
    mma_gemm<1><<<dim3(DD / 128, MROWS / 128), 256, SMEM_DYN>>>(
        (const __nv_bfloat16*)p_ah, (const __nv_bfloat16*)p_al,
        (const __nv_bfloat16*)p_w2ht, (const __nv_bfloat16*)p_w2lt,
        b2, out, DD, DD);
}

// round 5
// speedup vs baseline: 2.4991x; 1.8086x over previous
#include <cuda_runtime.h>
#include <cuda_bf16.h>
#include <cstdint>
#include <math.h>

// Problem constants
#define BB 2
#define SS 2048
#define DD 1024
#define HH 16
#define HD 64
#define BH (BB*HH)          // 32
#define MROWS (BB*SS)       // 4096
#define LOG2E 1.4426950408889634f

// ---------------------------------------------------------------------------
// Scratch (static device globals: allocation-free)
// ---------------------------------------------------------------------------
__device__ __nv_bfloat16 g_qh[BH*SS*HD];
__device__ __nv_bfloat16 g_ql[BH*SS*HD];
__device__ __nv_bfloat16 g_kh[BH*SS*HD];
__device__ __nv_bfloat16 g_kl[BH*SS*HD];
__device__ __nv_bfloat16 g_vh[BH*SS*HD];
__device__ __nv_bfloat16 g_vl[BH*SS*HD];
__device__ __nv_bfloat16 g_xh [MROWS*DD];
__device__ __nv_bfloat16 g_xl [MROWS*DD];
__device__ __nv_bfloat16 g_w1ht[3*DD*DD];
__device__ __nv_bfloat16 g_w1lt[3*DD*DD];
__device__ __nv_bfloat16 g_w2ht[DD*DD];
__device__ __nv_bfloat16 g_w2lt[DD*DD];
__device__ __nv_bfloat16 g_ah [MROWS*DD];
__device__ __nv_bfloat16 g_al [MROWS*DD];

// ---------------------------------------------------------------------------
// PTX helpers (sm_80-portable: mma.sync / ldmatrix / cp.async)
// ---------------------------------------------------------------------------
__device__ __forceinline__ uint32_t smem_to_u32(const void* p) {
    uint32_t a;
    asm("{ .reg .u64 t; cvta.to.shared.u64 t, %1; cvt.u32.u64 %0, t; }"
        : "=r"(a) : "l"(p));
    return a;
}
__device__ __forceinline__ void ldsm_x4(uint32_t* r, uint32_t addr) {
    asm volatile("ldmatrix.sync.aligned.m8n8.x4.shared.b16 {%0,%1,%2,%3}, [%4];"
                 : "=r"(r[0]), "=r"(r[1]), "=r"(r[2]), "=r"(r[3]) : "r"(addr));
}
__device__ __forceinline__ void ldsm_x4_t(uint32_t* r, uint32_t addr) {
    asm volatile("ldmatrix.sync.aligned.m8n8.x4.trans.shared.b16 {%0,%1,%2,%3}, [%4];"
                 : "=r"(r[0]), "=r"(r[1]), "=r"(r[2]), "=r"(r[3]) : "r"(addr));
}
__device__ __forceinline__ void mma_bf16(float* c, const uint32_t* a, uint32_t b0, uint32_t b1) {
    asm volatile(
        "mma.sync.aligned.m16n8k16.row.col.f32.bf16.bf16.f32 "
        "{%0,%1,%2,%3}, {%4,%5,%6,%7}, {%8,%9}, {%0,%1,%2,%3};"
        : "+f"(c[0]), "+f"(c[1]), "+f"(c[2]), "+f"(c[3])
        : "r"(a[0]), "r"(a[1]), "r"(a[2]), "r"(a[3]), "r"(b0), "r"(b1));
}
__device__ __forceinline__ void cp_async16(uint32_t saddr, const void* gptr) {
    asm volatile("cp.async.cg.shared.global [%0], [%1], 16;" :: "r"(saddr), "l"(gptr));
}
#define CP_COMMIT()  asm volatile("cp.async.commit_group;" ::: "memory")
#define CP_WAIT(n)   asm volatile("cp.async.wait_group %0;" :: "n"(n) : "memory")

// XOR swizzle inside 128B rows: element chunk c (16B) of row r
#define SWZ(r, c) ((uint32_t)(r)*128u + ((((uint32_t)(c)) ^ ((uint32_t)(r) & 7u)) << 4))

// Fast exp2 on FMA pipe (avoids MUFU throughput wall). t <= 0 expected.
__device__ __forceinline__ float fexp2(float t) {
    t = fmaxf(t, -126.0f);
    float kf = rintf(t);
    float f = t - kf;
    float p = 0.0013333558f;
    p = fmaf(p, f, 0.0096181291f);
    p = fmaf(p, f, 0.0555041087f);
    p = fmaf(p, f, 0.2402265069f);
    p = fmaf(p, f, 0.6931471806f);
    p = fmaf(p, f, 1.0f);
    return __int_as_float(__float_as_int(p) + (((int)kf) << 23));
}
__device__ __forceinline__ uint32_t pack_bf16(__nv_bfloat16 a, __nv_bfloat16 b) {
    return ((uint32_t)__bfloat16_as_ushort(b) << 16) | (uint32_t)__bfloat16_as_ushort(a);
}

// ---------------------------------------------------------------------------
// Conversion kernels
// ---------------------------------------------------------------------------
__global__ __launch_bounds__(256)
void split_kernel(const float* __restrict__ x, __nv_bfloat16* __restrict__ xh,
                  __nv_bfloat16* __restrict__ xl)
{
    int i = (blockIdx.x * 256 + threadIdx.x) * 4;
    float4 v = *reinterpret_cast<const float4*>(x + i);
    float a[4] = {v.x, v.y, v.z, v.w};
    #pragma unroll
    for (int j = 0; j < 4; j++) {
        __nv_bfloat16 h = __float2bfloat16(a[j]);
        xh[i + j] = h;
        xl[i + j] = __float2bfloat16(a[j] - __bfloat162float(h));
    }
}

__global__ __launch_bounds__(256)
void tsplit_kernel(const float* __restrict__ W, __nv_bfloat16* __restrict__ WTh,
                   __nv_bfloat16* __restrict__ WTl, int K, int N)
{
    __shared__ float t[32][33];
    const int k0 = blockIdx.y * 32, n0 = blockIdx.x * 32;
    const int tx = threadIdx.x & 31, ty = threadIdx.x >> 5;
    #pragma unroll
    for (int i = 0; i < 4; i++)
        t[ty + i * 8][tx] = W[(size_t)(k0 + ty + i * 8) * N + n0 + tx];
    __syncthreads();
    #pragma unroll
    for (int i = 0; i < 4; i++) {
        int n = ty + i * 8;
        float v = t[tx][n];
        __nv_bfloat16 h = __float2bfloat16(v);
        WTh[(size_t)(n0 + n) * K + k0 + tx] = h;
        WTl[(size_t)(n0 + n) * K + k0 + tx] = __float2bfloat16(v - __bfloat162float(h));
    }
}

// ---------------------------------------------------------------------------
// mma.sync GEMM (as R4). EPI=0: split-bf16 scatter into Q/K/V. EPI=1: fp32 C.
// ---------------------------------------------------------------------------
#define TILE_B  10240
#define STAGE_B 40960

template<int EPI>
__global__ __launch_bounds__(256, 1)
void mma_gemm(const __nv_bfloat16* __restrict__ Ah, const __nv_bfloat16* __restrict__ Al,
              const __nv_bfloat16* __restrict__ Bh, const __nv_bfloat16* __restrict__ Bl,
              const float* __restrict__ bias, float* __restrict__ C,
              int N, int K)
{
    extern __shared__ char dsm[];
    const uint32_t sb = smem_to_u32(dsm);

    const int tid = threadIdx.x;
    const int wid = tid >> 5;
    const int lane = tid & 31;
    const int bm = blockIdx.y;
    const int bn = blockIdx.x;
    const int wm = wid & 1;
    const int wn = wid >> 1;

    const __nv_bfloat16* gsrc[4];
    gsrc[0] = Ah + (size_t)bm * 128 * K;
    gsrc[1] = Al + (size_t)bm * 128 * K;
    gsrc[2] = Bh + (size_t)bn * 128 * K;
    gsrc[3] = Bl + (size_t)bn * 128 * K;

    const int l_row0 = tid >> 2;
    const int l_c16  = tid & 3;

    auto load_stage = [&](int stage, int k0) {
        uint32_t sdst = sb + stage * STAGE_B;
        #pragma unroll
        for (int op = 0; op < 4; op++) {
            const __nv_bfloat16* g = gsrc[op];
            #pragma unroll
            for (int h = 0; h < 2; h++) {
                int row = l_row0 + h * 64;
                cp_async16(sdst + op * TILE_B + row * 80 + l_c16 * 16,
                           g + (size_t)row * K + k0 + l_c16 * 8);
            }
        }
    };

    float acc[4][4][4];
    #pragma unroll
    for (int mt = 0; mt < 4; mt++)
        #pragma unroll
        for (int nt = 0; nt < 4; nt++)
            #pragma unroll
            for (int r = 0; r < 4; r++) acc[mt][nt][r] = 0.0f;

    const int NCH = K >> 5;

    load_stage(0, 0);
    CP_COMMIT();

    for (int c = 0; c < NCH; c++) {
        const int stage = c & 1;
        if (c + 1 < NCH) {
            load_stage((c + 1) & 1, (c + 1) * 32);
            CP_COMMIT();
            CP_WAIT(1);
        } else {
            CP_WAIT(0);
        }
        __syncthreads();

        const uint32_t sA_h = sb + stage * STAGE_B + 0 * TILE_B;
        const uint32_t sA_l = sb + stage * STAGE_B + 1 * TILE_B;
        const uint32_t sB_h = sb + stage * STAGE_B + 2 * TILE_B;
        const uint32_t sB_l = sb + stage * STAGE_B + 3 * TILE_B;

        #pragma unroll
        for (int ks = 0; ks < 2; ks++) {
            const int kbyte = ks * 32;
            uint32_t ah[4][4], al[4][4], bh[2][4], bl[2][4];

            #pragma unroll
            for (int mt = 0; mt < 4; mt++) {
                uint32_t roff = (uint32_t)(wm * 64 + mt * 16 + (lane & 15)) * 80
                              + (uint32_t)(lane >> 4) * 16 + kbyte;
                ldsm_x4(ah[mt], sA_h + roff);
                ldsm_x4(al[mt], sA_l + roff);
            }
            #pragma unroll
            for (int nt2 = 0; nt2 < 2; nt2++) {
                int g = lane >> 3;
                uint32_t roff = (uint32_t)(wn * 32 + nt2 * 16 + (lane & 7) + ((g >> 1) << 3)) * 80
                              + (uint32_t)(g & 1) * 16 + kbyte;
                ldsm_x4(bh[nt2], sB_h + roff);
                ldsm_x4(bl[nt2], sB_l + roff);
            }

            #pragma unroll
            for (int mt = 0; mt < 4; mt++)
                #pragma unroll
                for (int nt = 0; nt < 4; nt++) {
                    const int nt2 = nt >> 1;
                    const int sel = (nt & 1) * 2;
                    mma_bf16(acc[mt][nt], ah[mt], bh[nt2][sel], bh[nt2][sel + 1]);
                    mma_bf16(acc[mt][nt], ah[mt], bl[nt2][sel], bl[nt2][sel + 1]);
                    mma_bf16(acc[mt][nt], al[mt], bh[nt2][sel], bh[nt2][sel + 1]);
                }
        }
        __syncthreads();
    }

    #pragma unroll
    for (int mt = 0; mt < 4; mt++) {
        #pragma unroll
        for (int nt = 0; nt < 4; nt++) {
            #pragma unroll
            for (int r = 0; r < 4; r++) {
                int m = bm * 128 + wm * 64 + mt * 16 + (lane >> 2) + (r >> 1) * 8;
                int n = bn * 128 + wn * 32 + nt * 8 + (lane & 3) * 2 + (r & 1);
                float v = acc[mt][nt][r] + __ldg(&bias[n]);
                if (EPI == 0) {
                    int part = n >> 10;
                    if (part == 0) v *= 0.125f * LOG2E;   // scale + exp2-domain fold
                    __nv_bfloat16 *dh, *dl;
                    if (part == 0)      { dh = g_qh; dl = g_ql; }
                    else if (part == 1) { dh = g_kh; dl = g_kl; }
                    else                { dh = g_vh; dl = g_vl; }
                    int b = m >> 11;
                    int s = m & 2047;
                    int col = n & 1023;
                    int hh = col >> 6;
                    int d = col & 63;
                    size_t idx = (((size_t)(b * 16 + hh) * 2048) + s) * 64 + d;
                    __nv_bfloat16 hi = __float2bfloat16(v);
                    dh[idx] = hi;
                    dl[idx] = __float2bfloat16(v - __bfloat162float(hi));
                } else {
                    C[(size_t)m * N + n] = v;
                }
            }
        }
    }
}

// ---------------------------------------------------------------------------
// Tensor-core flash attention. Bq=128, Bk=64, 8 warps (warp = 16 q-rows).
// Split-bf16 QK^T and PV (3 MMAs each), online softmax on fast exp2.
// smem: Qh/Ql 32KB + 2 stages x (Kh,Kl,Vh,Vl) 32KB = 96KB.
// ---------------------------------------------------------------------------
__global__ __launch_bounds__(256, 1)
void flash_mma()
{
    extern __shared__ char fsm[];
    const uint32_t sb = smem_to_u32(fsm);
    const uint32_t sQh = sb, sQl = sb + 16384;

    const int tid = threadIdx.x;
    const int lane = tid & 31;
    const int wid = tid >> 5;
    const int qt = 15 - blockIdx.x;       // heavy tiles first
    const int bh = blockIdx.y;

    const size_t qoff = ((size_t)bh * SS + qt * 128) * HD;

    auto load_Q = [&]() {
        #pragma unroll
        for (int i = 0; i < 4; i++) {
            int ch = tid + i * 256;
            int r = ch >> 3, c = ch & 7;
            cp_async16(sQh + SWZ(r, c), g_qh + qoff + (size_t)r * 64 + c * 8);
            cp_async16(sQl + SWZ(r, c), g_ql + qoff + (size_t)r * 64 + c * 8);
        }
    };
    auto load_KV = [&](int stage, int kt) {
        uint32_t sbase = sb + 32768 + stage * 32768;
        size_t off = ((size_t)bh * SS + kt * 64) * HD;
        const __nv_bfloat16* srcs[4] = { g_kh + off, g_kl + off, g_vh + off, g_vl + off };
        #pragma unroll
        for (int b = 0; b < 4; b++)
            #pragma unroll
            for (int i = 0; i < 2; i++) {
                int ch = tid + i * 256;
                int r = ch >> 3, c = ch & 7;
                cp_async16(sbase + b * 8192 + SWZ(r, c), srcs[b] + (size_t)r * 64 + c * 8);
            }
    };

    const int nkt = 2 * qt + 2;

    load_Q();
    load_KV(0, 0);
    CP_COMMIT();

    uint32_t qh[4][4], ql[4][4];
    float oacc[8][4];
    #pragma unroll
    for (int nt = 0; nt < 8; nt++)
        #pragma unroll
        for (int j = 0; j < 4; j++) oacc[nt][j] = 0.0f;
    float m_s[2] = {-1e30f, -1e30f};
    float l_s[2] = {0.0f, 0.0f};

    for (int kt = 0; kt < nkt; kt++) {
        const int stage = kt & 1;
        if (kt + 1 < nkt) {
            load_KV((kt + 1) & 1, kt + 1);
            CP_COMMIT();
            CP_WAIT(1);
        } else {
            CP_WAIT(0);
        }
        __syncthreads();

        if (kt == 0) {
            // extract Q fragments once (rows = wid*16 + lane%16)
            #pragma unroll
            for (int t = 0; t < 4; t++) {
                int row = wid * 16 + (lane & 15);
                int c = t * 2 + (lane >> 4);
                ldsm_x4(qh[t], sQh + SWZ(row, c));
                ldsm_x4(ql[t], sQl + SWZ(row, c));
            }
        }

        const uint32_t stKh = sb + 32768 + stage * 32768;
        const uint32_t stKl = stKh + 8192;
        const uint32_t stVh = stKh + 16384;
        const uint32_t stVl = stKh + 24576;

        // ---- scores S = Q K^T (exp2-domain; scale folded into Q) ----
        float sacc[8][4];
        #pragma unroll
        for (int nt = 0; nt < 8; nt++)
            #pragma unroll
            for (int j = 0; j < 4; j++) sacc[nt][j] = 0.0f;

        #pragma unroll
        for (int t = 0; t < 4; t++) {
            #pragma unroll
            for (int p = 0; p < 4; p++) {
                int g = lane >> 3;
                int row = p * 16 + (lane & 7) + ((g >> 1) << 3);
                int c = t * 2 + (g & 1);
                uint32_t kh4[4], kl4[4];
                ldsm_x4(kh4, stKh + SWZ(row, c));
                ldsm_x4(kl4, stKl + SWZ(row, c));
                mma_bf16(sacc[2*p],   qh[t], kh4[0], kh4[1]);
                mma_bf16(sacc[2*p],   qh[t], kl4[0], kl4[1]);
                mma_bf16(sacc[2*p],   ql[t], kh4[0], kh4[1]);
                mma_bf16(sacc[2*p+1], qh[t], kh4[2], kh4[3]);
                mma_bf16(sacc[2*p+1], qh[t], kl4[2], kl4[3]);
                mma_bf16(sacc[2*p+1], ql[t], kh4[2], kh4[3]);
            }
        }

        // ---- causal mask (only the two diagonal-adjacent tiles) ----
        if (kt >= 2 * qt) {
            int r0 = qt * 128 + wid * 16 + (lane >> 2);
            #pragma unroll
            for (int nt = 0; nt < 8; nt++)
                #pragma unroll
                for (int j = 0; j < 4; j++) {
                    int row = r0 + (j >> 1) * 8;
                    int col = kt * 64 + nt * 8 + (lane & 3) * 2 + (j & 1);
                    if (col > row) sacc[nt][j] = -1e30f;
                }
        }

        // ---- online softmax (fast exp2 on FMA pipe) ----
        float rmax[2] = {-1e30f, -1e30f};
        #pragma unroll
        for (int nt = 0; nt < 8; nt++) {
            rmax[0] = fmaxf(rmax[0], fmaxf(sacc[nt][0], sacc[nt][1]));
            rmax[1] = fmaxf(rmax[1], fmaxf(sacc[nt][2], sacc[nt][3]));
        }
        #pragma unroll
        for (int h = 0; h < 2; h++) {
            rmax[h] = fmaxf(rmax[h], __shfl_xor_sync(0xffffffffu, rmax[h], 1));
            rmax[h] = fmaxf(rmax[h], __shfl_xor_sync(0xffffffffu, rmax[h], 2));
        }
        float corr[2], mnew[2];
        #pragma unroll
        for (int h = 0; h < 2; h++) {
            mnew[h] = fmaxf(m_s[h], rmax[h]);
            corr[h] = fexp2(m_s[h] - mnew[h]);
            m_s[h] = mnew[h];
        }

        uint32_t phpk[8][2], plpk[8][2];
        float rsum[2] = {0.0f, 0.0f};
        #pragma unroll
        for (int nt = 0; nt < 8; nt++) {
            #pragma unroll
            for (int h = 0; h < 2; h++) {
                float p0 = fexp2(sacc[nt][2*h]   - m_s[h]);
                float p1 = fexp2(sacc[nt][2*h+1] - m_s[h]);
                rsum[h] += p0 + p1;
                __nv_bfloat16 h0 = __float2bfloat16(p0);
                __nv_bfloat16 h1 = __float2bfloat16(p1);
                phpk[nt][h] = pack_bf16(h0, h1);
                plpk[nt][h] = pack_bf16(
                    __float2bfloat16(p0 - __bfloat162float(h0)),
                    __float2bfloat16(p1 - __bfloat162float(h1)));
            }
        }
        #pragma unroll
        for (int h = 0; h < 2; h++) {
            rsum[h] += __shfl_xor_sync(0xffffffffu, rsum[h], 1);
            rsum[h] += __shfl_xor_sync(0xffffffffu, rsum[h], 2);
            l_s[h] = l_s[h] * corr[h] + rsum[h];
        }
        #pragma unroll
        for (int nt = 0; nt < 8; nt++) {
            oacc[nt][0] *= corr[0];
            oacc[nt][1] *= corr[0];
            oacc[nt][2] *= corr[1];
            oacc[nt][3] *= corr[1];
        }

        // ---- O += P V ----
        #pragma unroll
        for (int t = 0; t < 4; t++) {
            uint32_t pa_h[4] = { phpk[2*t][0], phpk[2*t][1], phpk[2*t+1][0], phpk[2*t+1][1] };
            uint32_t pa_l[4] = { plpk[2*t][0], plpk[2*t][1], plpk[2*t+1][0], plpk[2*t+1][1] };
            #pragma unroll
            for (int p = 0; p < 4; p++) {
                int row = t * 16 + (lane & 15);
                int c = 2 * p + (lane >> 4);
                uint32_t vh4[4], vl4[4];
                ldsm_x4_t(vh4, stVh + SWZ(row, c));
                ldsm_x4_t(vl4, stVl + SWZ(row, c));
                mma_bf16(oacc[2*p],   pa_h, vh4[0], vh4[1]);
                mma_bf16(oacc[2*p],   pa_h, vl4[0], vl4[1]);
                mma_bf16(oacc[2*p],   pa_l, vh4[0], vh4[1]);
                mma_bf16(oacc[2*p+1], pa_h, vh4[2], vh4[3]);
                mma_bf16(oacc[2*p+1], pa_h, vl4[2], vl4[3]);
                mma_bf16(oacc[2*p+1], pa_l, vh4[2], vh4[3]);
            }
        }
        __syncthreads();
    }

    // ---- epilogue: O/l -> bf16 hi/lo split, merged-head layout ----
    const int b = bh >> 4;
    const int head = bh & 15;
    float inv[2] = {1.0f / l_s[0], 1.0f / l_s[1]};
    #pragma unroll
    for (int h = 0; h < 2; h++) {
        int srow = qt * 128 + wid * 16 + (lane >> 2) + h * 8;
        size_t base = ((size_t)(b * SS + srow)) * DD + head * 64 + (lane & 3) * 2;
        #pragma unroll
        for (int nt = 0; nt < 8; nt++) {
            float o0 = oacc[nt][2*h]   * inv[h];
            float o1 = oacc[nt][2*h+1] * inv[h];
            __nv_bfloat16 h0 = __float2bfloat16(o0);
            __nv_bfloat16 h1 = __float2bfloat16(o1);
            *reinterpret_cast<uint32_t*>(g_ah + base + nt * 8) = pack_bf16(h0, h1);
            *reinterpret_cast<uint32_t*>(g_al + base + nt * 8) = pack_bf16(
                __float2bfloat16(o0 - __bfloat162float(h0)),
                __float2bfloat16(o1 - __bfloat162float(h1)));
        }
    }
}

// ---------------------------------------------------------------------------
extern "C" void kernel_launch(void* const* d_in, const int* in_sizes, int n_in,
                              void* d_out, int out_size)
{
    (void)in_sizes; (void)n_in; (void)out_size;
    const float* x   = (const float*)d_in[0];
    const float* w1  = (const float*)d_in[1];
    const float* b1  = (const float*)d_in[2];
    const float* w2  = (const float*)d_in[3];
    const float* b2  = (const float*)d_in[4];
    float* out = (float*)d_out;

    const int SMEM_DYN = 2 * STAGE_B;          // 81920
    const int SMEM_FL  = 98304;                // 96KB
    cudaFuncSetAttribute(mma_gemm<0>, cudaFuncAttributeMaxDynamicSharedMemorySize, SMEM_DYN);
    cudaFuncSetAttribute(mma_gemm<1>, cudaFuncAttributeMaxDynamicSharedMemorySize, SMEM_DYN);
    cudaFuncSetAttribute(flash_mma, cudaFuncAttributeMaxDynamicSharedMemorySize, SMEM_FL);

    void *p_xh, *p_xl, *p_w1ht, *p_w1lt, *p_w2ht, *p_w2lt, *p_ah, *p_al;
    cudaGetSymbolAddress(&p_xh, g_xh);     cudaGetSymbolAddress(&p_xl, g_xl);
    cudaGetSymbolAddress(&p_w1ht, g_w1ht); cudaGetSymbolAddress(&p_w1lt, g_w1lt);
    cudaGetSymbolAddress(&p_w2ht, g_w2ht); cudaGetSymbolAddress(&p_w2lt, g_w2lt);
    cudaGetSymbolAddress(&p_ah, g_ah);     cudaGetSymbolAddress(&p_al, g_al);

    split_kernel<<<MROWS * DD / 1024, 256>>>(x, (__nv_bfloat16*)p_xh, (__nv_bfloat16*)p_xl);
    tsplit_kernel<<<dim3(3 * DD / 32, DD / 32), 256>>>(w1, (__nv_bfloat16*)p_w1ht,
                                                       (__nv_bfloat16*)p_w1lt, DD, 3 * DD);
    tsplit_kernel<<<dim3(DD / 32, DD / 32), 256>>>(w2, (__nv_bfloat16*)p_w2ht,
                                                   (__nv_bfloat16*)p_w2lt, DD, DD);

    mma_gemm<0><<<dim3(3 * DD / 128, MROWS / 128), 256, SMEM_DYN>>>(
        (const __nv_bfloat16*)p_xh, (const __nv_bfloat16*)p_xl,
        (const __nv_bfloat16*)p_w1ht, (const __nv_bfloat16*)p_w1lt,
        b1, nullptr, 3 * DD, DD);

    flash_mma<<<dim3(SS / 128, BH), 256, SMEM_FL>>>();

    mma_gemm<1><<<dim3(DD / 128, MROWS / 128), 256, SMEM_DYN>>>(
        (const __nv_bfloat16*)p_ah, (const __nv_bfloat16*)p_al,
        (const __nv_bfloat16*)p_w2ht, (const __nv_bfloat16*)p_w2lt,
        b2, out, DD, DD);
}

// round 6
// speedup vs baseline: 2.8181x; 1.1276x over previous
#include <cuda_runtime.h>
#include <cuda_bf16.h>
#include <cstdint>
#include <math.h>

// Problem constants
#define BB 2
#define SS 2048
#define DD 1024
#define HH 16
#define HD 64
#define BH (BB*HH)          // 32
#define MROWS (BB*SS)       // 4096
#define LOG2E 1.4426950408889634f

// ---------------------------------------------------------------------------
// Scratch (static device globals: allocation-free)
// ---------------------------------------------------------------------------
__device__ __nv_bfloat16 g_qh[BH*SS*HD];
__device__ __nv_bfloat16 g_ql[BH*SS*HD];
__device__ __nv_bfloat16 g_kh[BH*SS*HD];
__device__ __nv_bfloat16 g_kl[BH*SS*HD];
__device__ __nv_bfloat16 g_vh[BH*SS*HD];
__device__ __nv_bfloat16 g_vl[BH*SS*HD];
__device__ __nv_bfloat16 g_xh [MROWS*DD];
__device__ __nv_bfloat16 g_xl [MROWS*DD];
__device__ __nv_bfloat16 g_w1ht[3*DD*DD];
__device__ __nv_bfloat16 g_w1lt[3*DD*DD];
__device__ __nv_bfloat16 g_w2ht[DD*DD];
__device__ __nv_bfloat16 g_w2lt[DD*DD];
__device__ __nv_bfloat16 g_ah [MROWS*DD];
__device__ __nv_bfloat16 g_al [MROWS*DD];

// ---------------------------------------------------------------------------
// PTX helpers (sm_80-portable: mma.sync / ldmatrix / cp.async)
// ---------------------------------------------------------------------------
__device__ __forceinline__ uint32_t smem_to_u32(const void* p) {
    uint32_t a;
    asm("{ .reg .u64 t; cvta.to.shared.u64 t, %1; cvt.u32.u64 %0, t; }"
        : "=r"(a) : "l"(p));
    return a;
}
__device__ __forceinline__ void ldsm_x4(uint32_t* r, uint32_t addr) {
    asm volatile("ldmatrix.sync.aligned.m8n8.x4.shared.b16 {%0,%1,%2,%3}, [%4];"
                 : "=r"(r[0]), "=r"(r[1]), "=r"(r[2]), "=r"(r[3]) : "r"(addr));
}
__device__ __forceinline__ void ldsm_x4_t(uint32_t* r, uint32_t addr) {
    asm volatile("ldmatrix.sync.aligned.m8n8.x4.trans.shared.b16 {%0,%1,%2,%3}, [%4];"
                 : "=r"(r[0]), "=r"(r[1]), "=r"(r[2]), "=r"(r[3]) : "r"(addr));
}
__device__ __forceinline__ void mma_bf16(float* c, const uint32_t* a, uint32_t b0, uint32_t b1) {
    asm volatile(
        "mma.sync.aligned.m16n8k16.row.col.f32.bf16.bf16.f32 "
        "{%0,%1,%2,%3}, {%4,%5,%6,%7}, {%8,%9}, {%0,%1,%2,%3};"
        : "+f"(c[0]), "+f"(c[1]), "+f"(c[2]), "+f"(c[3])
        : "r"(a[0]), "r"(a[1]), "r"(a[2]), "r"(a[3]), "r"(b0), "r"(b1));
}
__device__ __forceinline__ void cp_async16(uint32_t saddr, const void* gptr) {
    asm volatile("cp.async.cg.shared.global [%0], [%1], 16;" :: "r"(saddr), "l"(gptr));
}
#define CP_COMMIT()  asm volatile("cp.async.commit_group;" ::: "memory")
#define CP_WAIT(n)   asm volatile("cp.async.wait_group %0;" :: "n"(n) : "memory")

// XOR swizzle inside 128B rows: element chunk c (16B) of row r
#define SWZ(r, c) ((uint32_t)(r)*128u + ((((uint32_t)(c)) ^ ((uint32_t)(r) & 7u)) << 4))

// Fast exp2 on FMA pipe (avoids MUFU throughput wall). t <= 0 expected.
__device__ __forceinline__ float fexp2(float t) {
    t = fmaxf(t, -126.0f);
    float kf = rintf(t);
    float f = t - kf;
    float p = 0.0013333558f;
    p = fmaf(p, f, 0.0096181291f);
    p = fmaf(p, f, 0.0555041087f);
    p = fmaf(p, f, 0.2402265069f);
    p = fmaf(p, f, 0.6931471806f);
    p = fmaf(p, f, 1.0f);
    return __int_as_float(__float_as_int(p) + (((int)kf) << 23));
}
__device__ __forceinline__ uint32_t pack_bf16(__nv_bfloat16 a, __nv_bfloat16 b) {
    return ((uint32_t)__bfloat16_as_ushort(b) << 16) | (uint32_t)__bfloat16_as_ushort(a);
}

// ---------------------------------------------------------------------------
// Conversion kernels
// ---------------------------------------------------------------------------
__global__ __launch_bounds__(256)
void split_kernel(const float* __restrict__ x, __nv_bfloat16* __restrict__ xh,
                  __nv_bfloat16* __restrict__ xl)
{
    int i = (blockIdx.x * 256 + threadIdx.x) * 4;
    float4 v = *reinterpret_cast<const float4*>(x + i);
    float a[4] = {v.x, v.y, v.z, v.w};
    #pragma unroll
    for (int j = 0; j < 4; j++) {
        __nv_bfloat16 h = __float2bfloat16(a[j]);
        xh[i + j] = h;
        xl[i + j] = __float2bfloat16(a[j] - __bfloat162float(h));
    }
}

__global__ __launch_bounds__(256)
void tsplit_kernel(const float* __restrict__ W, __nv_bfloat16* __restrict__ WTh,
                   __nv_bfloat16* __restrict__ WTl, int K, int N)
{
    __shared__ float t[32][33];
    const int k0 = blockIdx.y * 32, n0 = blockIdx.x * 32;
    const int tx = threadIdx.x & 31, ty = threadIdx.x >> 5;
    #pragma unroll
    for (int i = 0; i < 4; i++)
        t[ty + i * 8][tx] = W[(size_t)(k0 + ty + i * 8) * N + n0 + tx];
    __syncthreads();
    #pragma unroll
    for (int i = 0; i < 4; i++) {
        int n = ty + i * 8;
        float v = t[tx][n];
        __nv_bfloat16 h = __float2bfloat16(v);
        WTh[(size_t)(n0 + n) * K + k0 + tx] = h;
        WTl[(size_t)(n0 + n) * K + k0 + tx] = __float2bfloat16(v - __bfloat162float(h));
    }
}

// ---------------------------------------------------------------------------
// mma.sync GEMM, register-lean variant for 2 CTAs/SM.
// BM=BN=128, BK=32, 8 warps (2x4), warp tile 64x32, cp.async double buffer.
// Fragments are transient: B-frags per ks, A-frags per mt.
// EPI=0: split-bf16 scatter into Q/K/V (Q scaled into exp2 domain). EPI=1: fp32 C.
// ---------------------------------------------------------------------------
#define TILE_B  10240
#define STAGE_B 40960

template<int EPI>
__global__ __launch_bounds__(256, 2)
void mma_gemm(const __nv_bfloat16* __restrict__ Ah, const __nv_bfloat16* __restrict__ Al,
              const __nv_bfloat16* __restrict__ Bh, const __nv_bfloat16* __restrict__ Bl,
              const float* __restrict__ bias, float* __restrict__ C,
              int N, int K)
{
    extern __shared__ char dsm[];
    const uint32_t sb = smem_to_u32(dsm);

    const int tid = threadIdx.x;
    const int wid = tid >> 5;
    const int lane = tid & 31;
    const int bm = blockIdx.y;
    const int bn = blockIdx.x;
    const int wm = wid & 1;
    const int wn = wid >> 1;

    const __nv_bfloat16* gsrc[4];
    gsrc[0] = Ah + (size_t)bm * 128 * K;
    gsrc[1] = Al + (size_t)bm * 128 * K;
    gsrc[2] = Bh + (size_t)bn * 128 * K;
    gsrc[3] = Bl + (size_t)bn * 128 * K;

    const int l_row0 = tid >> 2;
    const int l_c16  = tid & 3;

    auto load_stage = [&](int stage, int k0) {
        uint32_t sdst = sb + stage * STAGE_B;
        #pragma unroll
        for (int op = 0; op < 4; op++) {
            const __nv_bfloat16* g = gsrc[op];
            #pragma unroll
            for (int h = 0; h < 2; h++) {
                int row = l_row0 + h * 64;
                cp_async16(sdst + op * TILE_B + row * 80 + l_c16 * 16,
                           g + (size_t)row * K + k0 + l_c16 * 8);
            }
        }
    };

    float acc[4][4][4];
    #pragma unroll
    for (int mt = 0; mt < 4; mt++)
        #pragma unroll
        for (int nt = 0; nt < 4; nt++)
            #pragma unroll
            for (int r = 0; r < 4; r++) acc[mt][nt][r] = 0.0f;

    const int NCH = K >> 5;

    load_stage(0, 0);
    CP_COMMIT();

    // precomputed intra-tile fragment offsets
    const uint32_t a_off = (uint32_t)(wm * 64 + (lane & 15)) * 80 + (uint32_t)(lane >> 4) * 16;
    const int bg = lane >> 3;
    const uint32_t b_off = (uint32_t)(wn * 32 + (lane & 7) + ((bg >> 1) << 3)) * 80
                         + (uint32_t)(bg & 1) * 16;

    for (int c = 0; c < NCH; c++) {
        const int stage = c & 1;
        if (c + 1 < NCH) {
            load_stage((c + 1) & 1, (c + 1) * 32);
            CP_COMMIT();
            CP_WAIT(1);
        } else {
            CP_WAIT(0);
        }
        __syncthreads();

        const uint32_t sA_h = sb + stage * STAGE_B + 0 * TILE_B;
        const uint32_t sA_l = sb + stage * STAGE_B + 1 * TILE_B;
        const uint32_t sB_h = sb + stage * STAGE_B + 2 * TILE_B;
        const uint32_t sB_l = sb + stage * STAGE_B + 3 * TILE_B;

        #pragma unroll
        for (int ks = 0; ks < 2; ks++) {
            const uint32_t kbyte = ks * 32;
            uint32_t bhf[2][4], blf[2][4];
            #pragma unroll
            for (int nt2 = 0; nt2 < 2; nt2++) {
                uint32_t roff = b_off + (uint32_t)nt2 * 16 * 80 + kbyte;
                ldsm_x4(bhf[nt2], sB_h + roff);
                ldsm_x4(blf[nt2], sB_l + roff);
            }
            #pragma unroll
            for (int mt = 0; mt < 4; mt++) {
                uint32_t ahf[4], alf[4];
                uint32_t roff = a_off + (uint32_t)mt * 16 * 80 + kbyte;
                ldsm_x4(ahf, sA_h + roff);
                ldsm_x4(alf, sA_l + roff);
                #pragma unroll
                for (int nt = 0; nt < 4; nt++) {
                    const int nt2 = nt >> 1;
                    const int sel = (nt & 1) * 2;
                    mma_bf16(acc[mt][nt], ahf, bhf[nt2][sel], bhf[nt2][sel + 1]);
                    mma_bf16(acc[mt][nt], ahf, blf[nt2][sel], blf[nt2][sel + 1]);
                    mma_bf16(acc[mt][nt], alf, bhf[nt2][sel], bhf[nt2][sel + 1]);
                }
            }
        }
        __syncthreads();
    }

    #pragma unroll
    for (int mt = 0; mt < 4; mt++) {
        #pragma unroll
        for (int nt = 0; nt < 4; nt++) {
            #pragma unroll
            for (int r = 0; r < 4; r++) {
                int m = bm * 128 + wm * 64 + mt * 16 + (lane >> 2) + (r >> 1) * 8;
                int n = bn * 128 + wn * 32 + nt * 8 + (lane & 3) * 2 + (r & 1);
                float v = acc[mt][nt][r] + __ldg(&bias[n]);
                if (EPI == 0) {
                    int part = n >> 10;
                    if (part == 0) v *= 0.125f * LOG2E;   // scale + exp2-domain fold
                    __nv_bfloat16 *dh, *dl;
                    if (part == 0)      { dh = g_qh; dl = g_ql; }
                    else if (part == 1) { dh = g_kh; dl = g_kl; }
                    else                { dh = g_vh; dl = g_vl; }
                    int b = m >> 11;
                    int s = m & 2047;
                    int col = n & 1023;
                    int hh = col >> 6;
                    int d = col & 63;
                    size_t idx = (((size_t)(b * 16 + hh) * 2048) + s) * 64 + d;
                    __nv_bfloat16 hi = __float2bfloat16(v);
                    dh[idx] = hi;
                    dl[idx] = __float2bfloat16(v - __bfloat162float(hi));
                } else {
                    C[(size_t)m * N + n] = v;
                }
            }
        }
    }
}

// ---------------------------------------------------------------------------
// Tensor-core flash attention (unchanged from R5).
// Bq=128, Bk=64, 8 warps (warp = 16 q-rows). Split-bf16 QK^T and PV.
// ---------------------------------------------------------------------------
__global__ __launch_bounds__(256, 1)
void flash_mma()
{
    extern __shared__ char fsm[];
    const uint32_t sb = smem_to_u32(fsm);
    const uint32_t sQh = sb, sQl = sb + 16384;

    const int tid = threadIdx.x;
    const int lane = tid & 31;
    const int wid = tid >> 5;
    const int qt = 15 - blockIdx.x;       // heavy tiles first
    const int bh = blockIdx.y;

    const size_t qoff = ((size_t)bh * SS + qt * 128) * HD;

    auto load_Q = [&]() {
        #pragma unroll
        for (int i = 0; i < 4; i++) {
            int ch = tid + i * 256;
            int r = ch >> 3, c = ch & 7;
            cp_async16(sQh + SWZ(r, c), g_qh + qoff + (size_t)r * 64 + c * 8);
            cp_async16(sQl + SWZ(r, c), g_ql + qoff + (size_t)r * 64 + c * 8);
        }
    };
    auto load_KV = [&](int stage, int kt) {
        uint32_t sbase = sb + 32768 + stage * 32768;
        size_t off = ((size_t)bh * SS + kt * 64) * HD;
        const __nv_bfloat16* srcs[4] = { g_kh + off, g_kl + off, g_vh + off, g_vl + off };
        #pragma unroll
        for (int b = 0; b < 4; b++)
            #pragma unroll
            for (int i = 0; i < 2; i++) {
                int ch = tid + i * 256;
                int r = ch >> 3, c = ch & 7;
                cp_async16(sbase + b * 8192 + SWZ(r, c), srcs[b] + (size_t)r * 64 + c * 8);
            }
    };

    const int nkt = 2 * qt + 2;

    load_Q();
    load_KV(0, 0);
    CP_COMMIT();

    uint32_t qh[4][4], ql[4][4];
    float oacc[8][4];
    #pragma unroll
    for (int nt = 0; nt < 8; nt++)
        #pragma unroll
        for (int j = 0; j < 4; j++) oacc[nt][j] = 0.0f;
    float m_s[2] = {-1e30f, -1e30f};
    float l_s[2] = {0.0f, 0.0f};

    for (int kt = 0; kt < nkt; kt++) {
        const int stage = kt & 1;
        if (kt + 1 < nkt) {
            load_KV((kt + 1) & 1, kt + 1);
            CP_COMMIT();
            CP_WAIT(1);
        } else {
            CP_WAIT(0);
        }
        __syncthreads();

        if (kt == 0) {
            #pragma unroll
            for (int t = 0; t < 4; t++) {
                int row = wid * 16 + (lane & 15);
                int c = t * 2 + (lane >> 4);
                ldsm_x4(qh[t], sQh + SWZ(row, c));
                ldsm_x4(ql[t], sQl + SWZ(row, c));
            }
        }

        const uint32_t stKh = sb + 32768 + stage * 32768;
        const uint32_t stKl = stKh + 8192;
        const uint32_t stVh = stKh + 16384;
        const uint32_t stVl = stKh + 24576;

        float sacc[8][4];
        #pragma unroll
        for (int nt = 0; nt < 8; nt++)
            #pragma unroll
            for (int j = 0; j < 4; j++) sacc[nt][j] = 0.0f;

        #pragma unroll
        for (int t = 0; t < 4; t++) {
            #pragma unroll
            for (int p = 0; p < 4; p++) {
                int g = lane >> 3;
                int row = p * 16 + (lane & 7) + ((g >> 1) << 3);
                int c = t * 2 + (g & 1);
                uint32_t kh4[4], kl4[4];
                ldsm_x4(kh4, stKh + SWZ(row, c));
                ldsm_x4(kl4, stKl + SWZ(row, c));
                mma_bf16(sacc[2*p],   qh[t], kh4[0], kh4[1]);
                mma_bf16(sacc[2*p],   qh[t], kl4[0], kl4[1]);
                mma_bf16(sacc[2*p],   ql[t], kh4[0], kh4[1]);
                mma_bf16(sacc[2*p+1], qh[t], kh4[2], kh4[3]);
                mma_bf16(sacc[2*p+1], qh[t], kl4[2], kl4[3]);
                mma_bf16(sacc[2*p+1], ql[t], kh4[2], kh4[3]);
            }
        }

        if (kt >= 2 * qt) {
            int r0 = qt * 128 + wid * 16 + (lane >> 2);
            #pragma unroll
            for (int nt = 0; nt < 8; nt++)
                #pragma unroll
                for (int j = 0; j < 4; j++) {
                    int row = r0 + (j >> 1) * 8;
                    int col = kt * 64 + nt * 8 + (lane & 3) * 2 + (j & 1);
                    if (col > row) sacc[nt][j] = -1e30f;
                }
        }

        float rmax[2] = {-1e30f, -1e30f};
        #pragma unroll
        for (int nt = 0; nt < 8; nt++) {
            rmax[0] = fmaxf(rmax[0], fmaxf(sacc[nt][0], sacc[nt][1]));
            rmax[1] = fmaxf(rmax[1], fmaxf(sacc[nt][2], sacc[nt][3]));
        }
        #pragma unroll
        for (int h = 0; h < 2; h++) {
            rmax[h] = fmaxf(rmax[h], __shfl_xor_sync(0xffffffffu, rmax[h], 1));
            rmax[h] = fmaxf(rmax[h], __shfl_xor_sync(0xffffffffu, rmax[h], 2));
        }
        float corr[2];
        #pragma unroll
        for (int h = 0; h < 2; h++) {
            float mnew = fmaxf(m_s[h], rmax[h]);
            corr[h] = fexp2(m_s[h] - mnew);
            m_s[h] = mnew;
        }

        uint32_t phpk[8][2], plpk[8][2];
        float rsum[2] = {0.0f, 0.0f};
        #pragma unroll
        for (int nt = 0; nt < 8; nt++) {
            #pragma unroll
            for (int h = 0; h < 2; h++) {
                float p0 = fexp2(sacc[nt][2*h]   - m_s[h]);
                float p1 = fexp2(sacc[nt][2*h+1] - m_s[h]);
                rsum[h] += p0 + p1;
                __nv_bfloat16 h0 = __float2bfloat16(p0);
                __nv_bfloat16 h1 = __float2bfloat16(p1);
                phpk[nt][h] = pack_bf16(h0, h1);
                plpk[nt][h] = pack_bf16(
                    __float2bfloat16(p0 - __bfloat162float(h0)),
                    __float2bfloat16(p1 - __bfloat162float(h1)));
            }
        }
        #pragma unroll
        for (int h = 0; h < 2; h++) {
            rsum[h] += __shfl_xor_sync(0xffffffffu, rsum[h], 1);
            rsum[h] += __shfl_xor_sync(0xffffffffu, rsum[h], 2);
            l_s[h] = l_s[h] * corr[h] + rsum[h];
        }
        #pragma unroll
        for (int nt = 0; nt < 8; nt++) {
            oacc[nt][0] *= corr[0];
            oacc[nt][1] *= corr[0];
            oacc[nt][2] *= corr[1];
            oacc[nt][3] *= corr[1];
        }

        #pragma unroll
        for (int t = 0; t < 4; t++) {
            uint32_t pa_h[4] = { phpk[2*t][0], phpk[2*t][1], phpk[2*t+1][0], phpk[2*t+1][1] };
            uint32_t pa_l[4] = { plpk[2*t][0], plpk[2*t][1], plpk[2*t+1][0], plpk[2*t+1][1] };
            #pragma unroll
            for (int p = 0; p < 4; p++) {
                int row = t * 16 + (lane & 15);
                int c = 2 * p + (lane >> 4);
                uint32_t vh4[4], vl4[4];
                ldsm_x4_t(vh4, stVh + SWZ(row, c));
                ldsm_x4_t(vl4, stVl + SWZ(row, c));
                mma_bf16(oacc[2*p],   pa_h, vh4[0], vh4[1]);
                mma_bf16(oacc[2*p],   pa_h, vl4[0], vl4[1]);
                mma_bf16(oacc[2*p],   pa_l, vh4[0], vh4[1]);
                mma_bf16(oacc[2*p+1], pa_h, vh4[2], vh4[3]);
                mma_bf16(oacc[2*p+1], pa_h, vl4[2], vl4[3]);
                mma_bf16(oacc[2*p+1], pa_l, vh4[2], vh4[3]);
            }
        }
        __syncthreads();
    }

    const int b = bh >> 4;
    const int head = bh & 15;
    float inv[2] = {1.0f / l_s[0], 1.0f / l_s[1]};
    #pragma unroll
    for (int h = 0; h < 2; h++) {
        int srow = qt * 128 + wid * 16 + (lane >> 2) + h * 8;
        size_t base = ((size_t)(b * SS + srow)) * DD + head * 64 + (lane & 3) * 2;
        #pragma unroll
        for (int nt = 0; nt < 8; nt++) {
            float o0 = oacc[nt][2*h]   * inv[h];
            float o1 = oacc[nt][2*h+1] * inv[h];
            __nv_bfloat16 h0 = __float2bfloat16(o0);
            __nv_bfloat16 h1 = __float2bfloat16(o1);
            *reinterpret_cast<uint32_t*>(g_ah + base + nt * 8) = pack_bf16(h0, h1);
            *reinterpret_cast<uint32_t*>(g_al + base + nt * 8) = pack_bf16(
                __float2bfloat16(o0 - __bfloat162float(h0)),
                __float2bfloat16(o1 - __bfloat162float(h1)));
        }
    }
}

// ---------------------------------------------------------------------------
extern "C" void kernel_launch(void* const* d_in, const int* in_sizes, int n_in,
                              void* d_out, int out_size)
{
    (void)in_sizes; (void)n_in; (void)out_size;
    const float* x   = (const float*)d_in[0];
    const float* w1  = (const float*)d_in[1];
    const float* b1  = (const float*)d_in[2];
    const float* w2  = (const float*)d_in[3];
    const float* b2  = (const float*)d_in[4];
    float* out = (float*)d_out;

    const int SMEM_DYN = 2 * STAGE_B;          // 81920
    const int SMEM_FL  = 98304;                // 96KB
    cudaFuncSetAttribute(mma_gemm<0>, cudaFuncAttributeMaxDynamicSharedMemorySize, SMEM_DYN);
    cudaFuncSetAttribute(mma_gemm<1>, cudaFuncAttributeMaxDynamicSharedMemorySize, SMEM_DYN);
    cudaFuncSetAttribute(flash_mma, cudaFuncAttributeMaxDynamicSharedMemorySize, SMEM_FL);

    void *p_xh, *p_xl, *p_w1ht, *p_w1lt, *p_w2ht, *p_w2lt, *p_ah, *p_al;
    cudaGetSymbolAddress(&p_xh, g_xh);     cudaGetSymbolAddress(&p_xl, g_xl);
    cudaGetSymbolAddress(&p_w1ht, g_w1ht); cudaGetSymbolAddress(&p_w1lt, g_w1lt);
    cudaGetSymbolAddress(&p_w2ht, g_w2ht); cudaGetSymbolAddress(&p_w2lt, g_w2lt);
    cudaGetSymbolAddress(&p_ah, g_ah);     cudaGetSymbolAddress(&p_al, g_al);

    split_kernel<<<MROWS * DD / 1024, 256>>>(x, (__nv_bfloat16*)p_xh, (__nv_bfloat16*)p_xl);
    tsplit_kernel<<<dim3(3 * DD / 32, DD / 32), 256>>>(w1, (__nv_bfloat16*)p_w1ht,
                                                       (__nv_bfloat16*)p_w1lt, DD, 3 * DD);
    tsplit_kernel<<<dim3(DD / 32, DD / 32), 256>>>(w2, (__nv_bfloat16*)p_w2ht,
                                                   (__nv_bfloat16*)p_w2lt, DD, DD);

    mma_gemm<0><<<dim3(3 * DD / 128, MROWS / 128), 256, SMEM_DYN>>>(
        (const __nv_bfloat16*)p_xh, (const __nv_bfloat16*)p_xl,
        (const __nv_bfloat16*)p_w1ht, (const __nv_bfloat16*)p_w1lt,
        b1, nullptr, 3 * DD, DD);

    flash_mma<<<dim3(SS / 128, BH), 256, SMEM_FL>>>();

    mma_gemm<1><<<dim3(DD / 128, MROWS / 128), 256, SMEM_DYN>>>(
        (const __nv_bfloat16*)p_ah, (const __nv_bfloat16*)p_al,
        (const __nv_bfloat16*)p_w2ht, (const __nv_bfloat16*)p_w2lt,
        b2, out, DD, DD);
}

// round 7
// speedup vs baseline: 2.8281x; 1.0036x over previous
#include <cuda_runtime.h>
#include <cuda_bf16.h>
#include <cstdint>
#include <math.h>

// Problem constants
#define BB 2
#define SS 2048
#define DD 1024
#define HH 16
#define HD 64
#define BH (BB*HH)          // 32
#define MROWS (BB*SS)       // 4096
#define LOG2E 1.4426950408889634f

// ---------------------------------------------------------------------------
// Scratch (static device globals: allocation-free)
// ---------------------------------------------------------------------------
__device__ __nv_bfloat16 g_qh[BH*SS*HD];
__device__ __nv_bfloat16 g_ql[BH*SS*HD];
__device__ __nv_bfloat16 g_kh[BH*SS*HD];
__device__ __nv_bfloat16 g_kl[BH*SS*HD];
__device__ __nv_bfloat16 g_vh[BH*SS*HD];
__device__ __nv_bfloat16 g_vl[BH*SS*HD];
__device__ __nv_bfloat16 g_xh [MROWS*DD];
__device__ __nv_bfloat16 g_xl [MROWS*DD];
__device__ __nv_bfloat16 g_w1ht[3*DD*DD];
__device__ __nv_bfloat16 g_w1lt[3*DD*DD];
__device__ __nv_bfloat16 g_w2ht[DD*DD];
__device__ __nv_bfloat16 g_w2lt[DD*DD];
__device__ __nv_bfloat16 g_ah [MROWS*DD];
__device__ __nv_bfloat16 g_al [MROWS*DD];

// ---------------------------------------------------------------------------
// PTX helpers (sm_80-portable: mma.sync / ldmatrix / cp.async)
// ---------------------------------------------------------------------------
__device__ __forceinline__ uint32_t smem_to_u32(const void* p) {
    uint32_t a;
    asm("{ .reg .u64 t; cvta.to.shared.u64 t, %1; cvt.u32.u64 %0, t; }"
        : "=r"(a) : "l"(p));
    return a;
}
__device__ __forceinline__ void ldsm_x4(uint32_t* r, uint32_t addr) {
    asm volatile("ldmatrix.sync.aligned.m8n8.x4.shared.b16 {%0,%1,%2,%3}, [%4];"
                 : "=r"(r[0]), "=r"(r[1]), "=r"(r[2]), "=r"(r[3]) : "r"(addr));
}
__device__ __forceinline__ void ldsm_x4_t(uint32_t* r, uint32_t addr) {
    asm volatile("ldmatrix.sync.aligned.m8n8.x4.trans.shared.b16 {%0,%1,%2,%3}, [%4];"
                 : "=r"(r[0]), "=r"(r[1]), "=r"(r[2]), "=r"(r[3]) : "r"(addr));
}
__device__ __forceinline__ void mma_bf16(float* c, const uint32_t* a, uint32_t b0, uint32_t b1) {
    asm volatile(
        "mma.sync.aligned.m16n8k16.row.col.f32.bf16.bf16.f32 "
        "{%0,%1,%2,%3}, {%4,%5,%6,%7}, {%8,%9}, {%0,%1,%2,%3};"
        : "+f"(c[0]), "+f"(c[1]), "+f"(c[2]), "+f"(c[3])
        : "r"(a[0]), "r"(a[1]), "r"(a[2]), "r"(a[3]), "r"(b0), "r"(b1));
}
__device__ __forceinline__ void cp_async16(uint32_t saddr, const void* gptr) {
    asm volatile("cp.async.cg.shared.global [%0], [%1], 16;" :: "r"(saddr), "l"(gptr));
}
#define CP_COMMIT()  asm volatile("cp.async.commit_group;" ::: "memory")
#define CP_WAIT(n)   asm volatile("cp.async.wait_group %0;" :: "n"(n) : "memory")

// XOR swizzle inside 128B rows: element chunk c (16B) of row r
#define SWZ(r, c) ((uint32_t)(r)*128u + ((((uint32_t)(c)) ^ ((uint32_t)(r) & 7u)) << 4))

// Fast exp2 on FMA pipe (avoids MUFU throughput wall). t <= 0 expected.
__device__ __forceinline__ float fexp2(float t) {
    t = fmaxf(t, -126.0f);
    float kf = rintf(t);
    float f = t - kf;
    float p = 0.0013333558f;
    p = fmaf(p, f, 0.0096181291f);
    p = fmaf(p, f, 0.0555041087f);
    p = fmaf(p, f, 0.2402265069f);
    p = fmaf(p, f, 0.6931471806f);
    p = fmaf(p, f, 1.0f);
    return __int_as_float(__float_as_int(p) + (((int)kf) << 23));
}
__device__ __forceinline__ uint32_t pack_bf16(__nv_bfloat16 a, __nv_bfloat16 b) {
    return ((uint32_t)__bfloat16_as_ushort(b) << 16) | (uint32_t)__bfloat16_as_ushort(a);
}

// ---------------------------------------------------------------------------
// Conversion kernels
// ---------------------------------------------------------------------------
__global__ __launch_bounds__(256)
void split_kernel(const float* __restrict__ x, __nv_bfloat16* __restrict__ xh,
                  __nv_bfloat16* __restrict__ xl)
{
    int i = (blockIdx.x * 256 + threadIdx.x) * 4;
    float4 v = *reinterpret_cast<const float4*>(x + i);
    float a[4] = {v.x, v.y, v.z, v.w};
    #pragma unroll
    for (int j = 0; j < 4; j++) {
        __nv_bfloat16 h = __float2bfloat16(a[j]);
        xh[i + j] = h;
        xl[i + j] = __float2bfloat16(a[j] - __bfloat162float(h));
    }
}

__global__ __launch_bounds__(256)
void tsplit_kernel(const float* __restrict__ W, __nv_bfloat16* __restrict__ WTh,
                   __nv_bfloat16* __restrict__ WTl, int K, int N)
{
    __shared__ float t[32][33];
    const int k0 = blockIdx.y * 32, n0 = blockIdx.x * 32;
    const int tx = threadIdx.x & 31, ty = threadIdx.x >> 5;
    #pragma unroll
    for (int i = 0; i < 4; i++)
        t[ty + i * 8][tx] = W[(size_t)(k0 + ty + i * 8) * N + n0 + tx];
    __syncthreads();
    #pragma unroll
    for (int i = 0; i < 4; i++) {
        int n = ty + i * 8;
        float v = t[tx][n];
        __nv_bfloat16 h = __float2bfloat16(v);
        WTh[(size_t)(n0 + n) * K + k0 + tx] = h;
        WTl[(size_t)(n0 + n) * K + k0 + tx] = __float2bfloat16(v - __bfloat162float(h));
    }
}

// ---------------------------------------------------------------------------
// mma.sync GEMM, 2 CTAs/SM, product-major MMA ordering (dependency spacing).
// BM=BN=128, BK=32, 8 warps (2x4), warp tile 64x32, cp.async double buffer.
// EPI=0: split-bf16 scatter into Q/K/V (Q scaled into exp2 domain). EPI=1: fp32 C.
// ---------------------------------------------------------------------------
#define TILE_B  10240
#define STAGE_B 40960

template<int EPI>
__global__ __launch_bounds__(256, 2)
void mma_gemm(const __nv_bfloat16* __restrict__ Ah, const __nv_bfloat16* __restrict__ Al,
              const __nv_bfloat16* __restrict__ Bh, const __nv_bfloat16* __restrict__ Bl,
              const float* __restrict__ bias, float* __restrict__ C,
              int N, int K)
{
    extern __shared__ char dsm[];
    const uint32_t sb = smem_to_u32(dsm);

    const int tid = threadIdx.x;
    const int wid = tid >> 5;
    const int lane = tid & 31;
    const int bm = blockIdx.y;
    const int bn = blockIdx.x;
    const int wm = wid & 1;
    const int wn = wid >> 1;

    const __nv_bfloat16* gsrc[4];
    gsrc[0] = Ah + (size_t)bm * 128 * K;
    gsrc[1] = Al + (size_t)bm * 128 * K;
    gsrc[2] = Bh + (size_t)bn * 128 * K;
    gsrc[3] = Bl + (size_t)bn * 128 * K;

    const int l_row0 = tid >> 2;
    const int l_c16  = tid & 3;

    auto load_stage = [&](int stage, int k0) {
        uint32_t sdst = sb + stage * STAGE_B;
        #pragma unroll
        for (int op = 0; op < 4; op++) {
            const __nv_bfloat16* g = gsrc[op];
            #pragma unroll
            for (int h = 0; h < 2; h++) {
                int row = l_row0 + h * 64;
                cp_async16(sdst + op * TILE_B + row * 80 + l_c16 * 16,
                           g + (size_t)row * K + k0 + l_c16 * 8);
            }
        }
    };

    float acc[4][4][4];
    #pragma unroll
    for (int mt = 0; mt < 4; mt++)
        #pragma unroll
        for (int nt = 0; nt < 4; nt++)
            #pragma unroll
            for (int r = 0; r < 4; r++) acc[mt][nt][r] = 0.0f;

    const int NCH = K >> 5;

    load_stage(0, 0);
    CP_COMMIT();

    const uint32_t a_off = (uint32_t)(wm * 64 + (lane & 15)) * 80 + (uint32_t)(lane >> 4) * 16;
    const int bg = lane >> 3;
    const uint32_t b_off = (uint32_t)(wn * 32 + (lane & 7) + ((bg >> 1) << 3)) * 80
                         + (uint32_t)(bg & 1) * 16;

    for (int c = 0; c < NCH; c++) {
        const int stage = c & 1;
        if (c + 1 < NCH) {
            load_stage((c + 1) & 1, (c + 1) * 32);
            CP_COMMIT();
            CP_WAIT(1);
        } else {
            CP_WAIT(0);
        }
        __syncthreads();

        const uint32_t sA_h = sb + stage * STAGE_B + 0 * TILE_B;
        const uint32_t sA_l = sb + stage * STAGE_B + 1 * TILE_B;
        const uint32_t sB_h = sb + stage * STAGE_B + 2 * TILE_B;
        const uint32_t sB_l = sb + stage * STAGE_B + 3 * TILE_B;

        #pragma unroll
        for (int ks = 0; ks < 2; ks++) {
            const uint32_t kbyte = ks * 32;
            uint32_t bhf[2][4], blf[2][4];
            #pragma unroll
            for (int nt2 = 0; nt2 < 2; nt2++) {
                uint32_t roff = b_off + (uint32_t)nt2 * 16 * 80 + kbyte;
                ldsm_x4(bhf[nt2], sB_h + roff);
                ldsm_x4(blf[nt2], sB_l + roff);
            }
            #pragma unroll
            for (int mt = 0; mt < 4; mt++) {
                uint32_t ahf[4], alf[4];
                uint32_t roff = a_off + (uint32_t)mt * 16 * 80 + kbyte;
                ldsm_x4(ahf, sA_h + roff);
                ldsm_x4(alf, sA_l + roff);
                // product-major: dependent MMAs to the same acc are 4 apart
                #pragma unroll
                for (int nt = 0; nt < 4; nt++)
                    mma_bf16(acc[mt][nt], ahf, bhf[nt >> 1][(nt & 1) * 2], bhf[nt >> 1][(nt & 1) * 2 + 1]);
                #pragma unroll
                for (int nt = 0; nt < 4; nt++)
                    mma_bf16(acc[mt][nt], ahf, blf[nt >> 1][(nt & 1) * 2], blf[nt >> 1][(nt & 1) * 2 + 1]);
                #pragma unroll
                for (int nt = 0; nt < 4; nt++)
                    mma_bf16(acc[mt][nt], alf, bhf[nt >> 1][(nt & 1) * 2], bhf[nt >> 1][(nt & 1) * 2 + 1]);
            }
        }
        __syncthreads();
    }

    #pragma unroll
    for (int mt = 0; mt < 4; mt++) {
        #pragma unroll
        for (int nt = 0; nt < 4; nt++) {
            #pragma unroll
            for (int r = 0; r < 4; r++) {
                int m = bm * 128 + wm * 64 + mt * 16 + (lane >> 2) + (r >> 1) * 8;
                int n = bn * 128 + wn * 32 + nt * 8 + (lane & 3) * 2 + (r & 1);
                float v = acc[mt][nt][r] + __ldg(&bias[n]);
                if (EPI == 0) {
                    int part = n >> 10;
                    if (part == 0) v *= 0.125f * LOG2E;   // scale + exp2-domain fold
                    __nv_bfloat16 *dh, *dl;
                    if (part == 0)      { dh = g_qh; dl = g_ql; }
                    else if (part == 1) { dh = g_kh; dl = g_kl; }
                    else                { dh = g_vh; dl = g_vl; }
                    int b = m >> 11;
                    int s = m & 2047;
                    int col = n & 1023;
                    int hh = col >> 6;
                    int d = col & 63;
                    size_t idx = (((size_t)(b * 16 + hh) * 2048) + s) * 64 + d;
                    __nv_bfloat16 hi = __float2bfloat16(v);
                    dh[idx] = hi;
                    dl[idx] = __float2bfloat16(v - __bfloat162float(hi));
                } else {
                    C[(size_t)m * N + n] = v;
                }
            }
        }
    }
}

// ---------------------------------------------------------------------------
// Tensor-core flash attention, fragment-hoisted + product-major MMA ordering.
// Bq=128, Bk=64, 8 warps (warp = 16 q-rows). Split-bf16 QK^T and PV.
// ---------------------------------------------------------------------------
__global__ __launch_bounds__(256, 1)
void flash_mma()
{
    extern __shared__ char fsm[];
    const uint32_t sb = smem_to_u32(fsm);
    const uint32_t sQh = sb, sQl = sb + 16384;

    const int tid = threadIdx.x;
    const int lane = tid & 31;
    const int wid = tid >> 5;
    const int qt = 15 - blockIdx.x;       // heavy tiles first
    const int bh = blockIdx.y;

    const size_t qoff = ((size_t)bh * SS + qt * 128) * HD;

    auto load_Q = [&]() {
        #pragma unroll
        for (int i = 0; i < 4; i++) {
            int ch = tid + i * 256;
            int r = ch >> 3, c = ch & 7;
            cp_async16(sQh + SWZ(r, c), g_qh + qoff + (size_t)r * 64 + c * 8);
            cp_async16(sQl + SWZ(r, c), g_ql + qoff + (size_t)r * 64 + c * 8);
        }
    };
    auto load_KV = [&](int stage, int kt) {
        uint32_t sbase = sb + 32768 + stage * 32768;
        size_t off = ((size_t)bh * SS + kt * 64) * HD;
        const __nv_bfloat16* srcs[4] = { g_kh + off, g_kl + off, g_vh + off, g_vl + off };
        #pragma unroll
        for (int b = 0; b < 4; b++)
            #pragma unroll
            for (int i = 0; i < 2; i++) {
                int ch = tid + i * 256;
                int r = ch >> 3, c = ch & 7;
                cp_async16(sbase + b * 8192 + SWZ(r, c), srcs[b] + (size_t)r * 64 + c * 8);
            }
    };

    const int nkt = 2 * qt + 2;

    load_Q();
    load_KV(0, 0);
    CP_COMMIT();

    uint32_t qh[4][4], ql[4][4];
    float oacc[8][4];
    #pragma unroll
    for (int nt = 0; nt < 8; nt++)
        #pragma unroll
        for (int j = 0; j < 4; j++) oacc[nt][j] = 0.0f;
    float m_s[2] = {-1e30f, -1e30f};
    float l_s[2] = {0.0f, 0.0f};

    for (int kt = 0; kt < nkt; kt++) {
        const int stage = kt & 1;
        if (kt + 1 < nkt) {
            load_KV((kt + 1) & 1, kt + 1);
            CP_COMMIT();
            CP_WAIT(1);
        } else {
            CP_WAIT(0);
        }
        __syncthreads();

        if (kt == 0) {
            #pragma unroll
            for (int t = 0; t < 4; t++) {
                int row = wid * 16 + (lane & 15);
                int c = t * 2 + (lane >> 4);
                ldsm_x4(qh[t], sQh + SWZ(row, c));
                ldsm_x4(ql[t], sQl + SWZ(row, c));
            }
        }

        const uint32_t stKh = sb + 32768 + stage * 32768;
        const uint32_t stKl = stKh + 8192;
        const uint32_t stVh = stKh + 16384;
        const uint32_t stVl = stKh + 24576;

        float sacc[8][4];
        #pragma unroll
        for (int nt = 0; nt < 8; nt++)
            #pragma unroll
            for (int j = 0; j < 4; j++) sacc[nt][j] = 0.0f;

        // ---- S = Q K^T: hoist all K frags per k-chunk, product-major ----
        #pragma unroll
        for (int t = 0; t < 4; t++) {
            uint32_t kh4[4][4], kl4[4][4];
            const int g = lane >> 3;
            #pragma unroll
            for (int p = 0; p < 4; p++) {
                int row = p * 16 + (lane & 7) + ((g >> 1) << 3);
                int c = t * 2 + (g & 1);
                ldsm_x4(kh4[p], stKh + SWZ(row, c));
                ldsm_x4(kl4[p], stKl + SWZ(row, c));
            }
            #pragma unroll
            for (int p = 0; p < 4; p++) {
                mma_bf16(sacc[2*p],   qh[t], kh4[p][0], kh4[p][1]);
                mma_bf16(sacc[2*p+1], qh[t], kh4[p][2], kh4[p][3]);
            }
            #pragma unroll
            for (int p = 0; p < 4; p++) {
                mma_bf16(sacc[2*p],   qh[t], kl4[p][0], kl4[p][1]);
                mma_bf16(sacc[2*p+1], qh[t], kl4[p][2], kl4[p][3]);
            }
            #pragma unroll
            for (int p = 0; p < 4; p++) {
                mma_bf16(sacc[2*p],   ql[t], kh4[p][0], kh4[p][1]);
                mma_bf16(sacc[2*p+1], ql[t], kh4[p][2], kh4[p][3]);
            }
        }

        if (kt >= 2 * qt) {
            int r0 = qt * 128 + wid * 16 + (lane >> 2);
            #pragma unroll
            for (int nt = 0; nt < 8; nt++)
                #pragma unroll
                for (int j = 0; j < 4; j++) {
                    int row = r0 + (j >> 1) * 8;
                    int col = kt * 64 + nt * 8 + (lane & 3) * 2 + (j & 1);
                    if (col > row) sacc[nt][j] = -1e30f;
                }
        }

        float rmax[2] = {-1e30f, -1e30f};
        #pragma unroll
        for (int nt = 0; nt < 8; nt++) {
            rmax[0] = fmaxf(rmax[0], fmaxf(sacc[nt][0], sacc[nt][1]));
            rmax[1] = fmaxf(rmax[1], fmaxf(sacc[nt][2], sacc[nt][3]));
        }
        #pragma unroll
        for (int h = 0; h < 2; h++) {
            rmax[h] = fmaxf(rmax[h], __shfl_xor_sync(0xffffffffu, rmax[h], 1));
            rmax[h] = fmaxf(rmax[h], __shfl_xor_sync(0xffffffffu, rmax[h], 2));
        }
        float corr[2];
        #pragma unroll
        for (int h = 0; h < 2; h++) {
            float mnew = fmaxf(m_s[h], rmax[h]);
            corr[h] = fexp2(m_s[h] - mnew);
            m_s[h] = mnew;
        }

        uint32_t phpk[8][2], plpk[8][2];
        float rsum[2] = {0.0f, 0.0f};
        #pragma unroll
        for (int nt = 0; nt < 8; nt++) {
            #pragma unroll
            for (int h = 0; h < 2; h++) {
                float p0 = fexp2(sacc[nt][2*h]   - m_s[h]);
                float p1 = fexp2(sacc[nt][2*h+1] - m_s[h]);
                rsum[h] += p0 + p1;
                __nv_bfloat16 h0 = __float2bfloat16(p0);
                __nv_bfloat16 h1 = __float2bfloat16(p1);
                phpk[nt][h] = pack_bf16(h0, h1);
                plpk[nt][h] = pack_bf16(
                    __float2bfloat16(p0 - __bfloat162float(h0)),
                    __float2bfloat16(p1 - __bfloat162float(h1)));
            }
        }
        #pragma unroll
        for (int h = 0; h < 2; h++) {
            rsum[h] += __shfl_xor_sync(0xffffffffu, rsum[h], 1);
            rsum[h] += __shfl_xor_sync(0xffffffffu, rsum[h], 2);
            l_s[h] = l_s[h] * corr[h] + rsum[h];
        }
        #pragma unroll
        for (int nt = 0; nt < 8; nt++) {
            oacc[nt][0] *= corr[0];
            oacc[nt][1] *= corr[0];
            oacc[nt][2] *= corr[1];
            oacc[nt][3] *= corr[1];
        }

        // ---- O += P V: hoist all V frags per k-chunk, product-major ----
        #pragma unroll
        for (int t = 0; t < 4; t++) {
            uint32_t pa_h[4] = { phpk[2*t][0], phpk[2*t][1], phpk[2*t+1][0], phpk[2*t+1][1] };
            uint32_t pa_l[4] = { plpk[2*t][0], plpk[2*t][1], plpk[2*t+1][0], plpk[2*t+1][1] };
            uint32_t vh4[4][4], vl4[4][4];
            #pragma unroll
            for (int p = 0; p < 4; p++) {
                int row = t * 16 + (lane & 15);
                int c = 2 * p + (lane >> 4);
                ldsm_x4_t(vh4[p], stVh + SWZ(row, c));
                ldsm_x4_t(vl4[p], stVl + SWZ(row, c));
            }
            #pragma unroll
            for (int p = 0; p < 4; p++) {
                mma_bf16(oacc[2*p],   pa_h, vh4[p][0], vh4[p][1]);
                mma_bf16(oacc[2*p+1], pa_h, vh4[p][2], vh4[p][3]);
            }
            #pragma unroll
            for (int p = 0; p < 4; p++) {
                mma_bf16(oacc[2*p],   pa_h, vl4[p][0], vl4[p][1]);
                mma_bf16(oacc[2*p+1], pa_h, vl4[p][2], vl4[p][3]);
            }
            #pragma unroll
            for (int p = 0; p < 4; p++) {
                mma_bf16(oacc[2*p],   pa_l, vh4[p][0], vh4[p][1]);
                mma_bf16(oacc[2*p+1], pa_l, vh4[p][2], vh4[p][3]);
            }
        }
        __syncthreads();
    }

    const int b = bh >> 4;
    const int head = bh & 15;
    float inv[2] = {1.0f / l_s[0], 1.0f / l_s[1]};
    #pragma unroll
    for (int h = 0; h < 2; h++) {
        int srow = qt * 128 + wid * 16 + (lane >> 2) + h * 8;
        size_t base = ((size_t)(b * SS + srow)) * DD + head * 64 + (lane & 3) * 2;
        #pragma unroll
        for (int nt = 0; nt < 8; nt++) {
            float o0 = oacc[nt][2*h]   * inv[h];
            float o1 = oacc[nt][2*h+1] * inv[h];
            __nv_bfloat16 h0 = __float2bfloat16(o0);
            __nv_bfloat16 h1 = __float2bfloat16(o1);
            *reinterpret_cast<uint32_t*>(g_ah + base + nt * 8) = pack_bf16(h0, h1);
            *reinterpret_cast<uint32_t*>(g_al + base + nt * 8) = pack_bf16(
                __float2bfloat16(o0 - __bfloat162float(h0)),
                __float2bfloat16(o1 - __bfloat162float(h1)));
        }
    }
}

// ---------------------------------------------------------------------------
extern "C" void kernel_launch(void* const* d_in, const int* in_sizes, int n_in,
                              void* d_out, int out_size)
{
    (void)in_sizes; (void)n_in; (void)out_size;
    const float* x   = (const float*)d_in[0];
    const float* w1  = (const float*)d_in[1];
    const float* b1  = (const float*)d_in[2];
    const float* w2  = (const float*)d_in[3];
    const float* b2  = (const float*)d_in[4];
    float* out = (float*)d_out;

    const int SMEM_DYN = 2 * STAGE_B;          // 81920
    const int SMEM_FL  = 98304;                // 96KB
    cudaFuncSetAttribute(mma_gemm<0>, cudaFuncAttributeMaxDynamicSharedMemorySize, SMEM_DYN);
    cudaFuncSetAttribute(mma_gemm<1>, cudaFuncAttributeMaxDynamicSharedMemorySize, SMEM_DYN);
    cudaFuncSetAttribute(flash_mma, cudaFuncAttributeMaxDynamicSharedMemorySize, SMEM_FL);

    void *p_xh, *p_xl, *p_w1ht, *p_w1lt, *p_w2ht, *p_w2lt, *p_ah, *p_al;
    cudaGetSymbolAddress(&p_xh, g_xh);     cudaGetSymbolAddress(&p_xl, g_xl);
    cudaGetSymbolAddress(&p_w1ht, g_w1ht); cudaGetSymbolAddress(&p_w1lt, g_w1lt);
    cudaGetSymbolAddress(&p_w2ht, g_w2ht); cudaGetSymbolAddress(&p_w2lt, g_w2lt);
    cudaGetSymbolAddress(&p_ah, g_ah);     cudaGetSymbolAddress(&p_al, g_al);

    split_kernel<<<MROWS * DD / 1024, 256>>>(x, (__nv_bfloat16*)p_xh, (__nv_bfloat16*)p_xl);
    tsplit_kernel<<<dim3(3 * DD / 32, DD / 32), 256>>>(w1, (__nv_bfloat16*)p_w1ht,
                                                       (__nv_bfloat16*)p_w1lt, DD, 3 * DD);
    tsplit_kernel<<<dim3(DD / 32, DD / 32), 256>>>(w2, (__nv_bfloat16*)p_w2ht,
                                                   (__nv_bfloat16*)p_w2lt, DD, DD);

    mma_gemm<0><<<dim3(3 * DD / 128, MROWS / 128), 256, SMEM_DYN>>>(
        (const __nv_bfloat16*)p_xh, (const __nv_bfloat16*)p_xl,
        (const __nv_bfloat16*)p_w1ht, (const __nv_bfloat16*)p_w1lt,
        b1, nullptr, 3 * DD, DD);

    flash_mma<<<dim3(SS / 128, BH), 256, SMEM_FL>>>();

    mma_gemm<1><<<dim3(DD / 128, MROWS / 128), 256, SMEM_DYN>>>(
        (const __nv_bfloat16*)p_ah, (const __nv_bfloat16*)p_al,
        (const __nv_bfloat16*)p_w2ht, (const __nv_bfloat16*)p_w2lt,
        b2, out, DD, DD);
}

// round 8
// speedup vs baseline: 3.7269x; 1.3178x over previous
#include <cuda_runtime.h>
#include <cuda_fp16.h>
#include <cstdint>
#include <math.h>

// Problem constants
#define BB 2
#define SS 2048
#define DD 1024
#define HH 16
#define HD 64
#define BH (BB*HH)          // 32
#define MROWS (BB*SS)       // 4096
#define LOG2E 1.4426950408889634f

// ---------------------------------------------------------------------------
// Scratch (static device globals: allocation-free)
// ---------------------------------------------------------------------------
__device__ __half g_qh[BH*SS*HD];     // Q split hi (exp2-domain scaled)
__device__ __half g_ql[BH*SS*HD];     // Q split lo
__device__ __half g_k16[BH*SS*HD];    // K single fp16
__device__ __half g_v16[BH*SS*HD];    // V single fp16
__device__ __half g_xh [MROWS*DD];    // X split hi
__device__ __half g_xl [MROWS*DD];    // X split lo
__device__ __half g_w1t[3*DD*DD];     // W1^T single fp16 [3072,1024]
__device__ __half g_w2t[DD*DD];       // W2^T single fp16 [1024,1024]
__device__ __half g_ah [MROWS*DD];    // attn out split hi
__device__ __half g_al [MROWS*DD];    // attn out split lo

// ---------------------------------------------------------------------------
// PTX helpers (sm_80-portable: mma.sync / ldmatrix / cp.async)
// ---------------------------------------------------------------------------
__device__ __forceinline__ uint32_t smem_to_u32(const void* p) {
    uint32_t a;
    asm("{ .reg .u64 t; cvta.to.shared.u64 t, %1; cvt.u32.u64 %0, t; }"
        : "=r"(a) : "l"(p));
    return a;
}
__device__ __forceinline__ void ldsm_x4(uint32_t* r, uint32_t addr) {
    asm volatile("ldmatrix.sync.aligned.m8n8.x4.shared.b16 {%0,%1,%2,%3}, [%4];"
                 : "=r"(r[0]), "=r"(r[1]), "=r"(r[2]), "=r"(r[3]) : "r"(addr));
}
__device__ __forceinline__ void ldsm_x4_t(uint32_t* r, uint32_t addr) {
    asm volatile("ldmatrix.sync.aligned.m8n8.x4.trans.shared.b16 {%0,%1,%2,%3}, [%4];"
                 : "=r"(r[0]), "=r"(r[1]), "=r"(r[2]), "=r"(r[3]) : "r"(addr));
}
__device__ __forceinline__ void mma_f16(float* c, const uint32_t* a, uint32_t b0, uint32_t b1) {
    asm volatile(
        "mma.sync.aligned.m16n8k16.row.col.f32.f16.f16.f32 "
        "{%0,%1,%2,%3}, {%4,%5,%6,%7}, {%8,%9}, {%0,%1,%2,%3};"
        : "+f"(c[0]), "+f"(c[1]), "+f"(c[2]), "+f"(c[3])
        : "r"(a[0]), "r"(a[1]), "r"(a[2]), "r"(a[3]), "r"(b0), "r"(b1));
}
__device__ __forceinline__ void cp_async16(uint32_t saddr, const void* gptr) {
    asm volatile("cp.async.cg.shared.global [%0], [%1], 16;" :: "r"(saddr), "l"(gptr));
}
#define CP_COMMIT()  asm volatile("cp.async.commit_group;" ::: "memory")
#define CP_WAIT(n)   asm volatile("cp.async.wait_group %0;" :: "n"(n) : "memory")

// XOR swizzle inside 128B rows: element chunk c (16B) of row r
#define SWZ(r, c) ((uint32_t)(r)*128u + ((((uint32_t)(c)) ^ ((uint32_t)(r) & 7u)) << 4))

// Fast exp2 on FMA pipe. t <= 0 expected.
__device__ __forceinline__ float fexp2(float t) {
    t = fmaxf(t, -126.0f);
    float kf = rintf(t);
    float f = t - kf;
    float p = 0.0013333558f;
    p = fmaf(p, f, 0.0096181291f);
    p = fmaf(p, f, 0.0555041087f);
    p = fmaf(p, f, 0.2402265069f);
    p = fmaf(p, f, 0.6931471806f);
    p = fmaf(p, f, 1.0f);
    return __int_as_float(__float_as_int(p) + (((int)kf) << 23));
}
__device__ __forceinline__ uint32_t pack_f16(__half a, __half b) {
    return ((uint32_t)__half_as_ushort(b) << 16) | (uint32_t)__half_as_ushort(a);
}

// ---------------------------------------------------------------------------
// Conversion kernels
// ---------------------------------------------------------------------------
__global__ __launch_bounds__(256)
void split_kernel(const float* __restrict__ x, __half* __restrict__ xh,
                  __half* __restrict__ xl)
{
    int i = (blockIdx.x * 256 + threadIdx.x) * 4;
    float4 v = *reinterpret_cast<const float4*>(x + i);
    float a[4] = {v.x, v.y, v.z, v.w};
    #pragma unroll
    for (int j = 0; j < 4; j++) {
        __half h = __float2half_rn(a[j]);
        xh[i + j] = h;
        xl[i + j] = __float2half_rn(a[j] - __half2float(h));
    }
}

// W[K,N] fp32 -> WT single fp16 [N,K]
__global__ __launch_bounds__(256)
void tconv_kernel(const float* __restrict__ W, __half* __restrict__ WT, int K, int N)
{
    __shared__ float t[32][33];
    const int k0 = blockIdx.y * 32, n0 = blockIdx.x * 32;
    const int tx = threadIdx.x & 31, ty = threadIdx.x >> 5;
    #pragma unroll
    for (int i = 0; i < 4; i++)
        t[ty + i * 8][tx] = W[(size_t)(k0 + ty + i * 8) * N + n0 + tx];
    __syncthreads();
    #pragma unroll
    for (int i = 0; i < 4; i++) {
        int n = ty + i * 8;
        WT[(size_t)(n0 + n) * K + k0 + tx] = __float2half_rn(t[tx][n]);
    }
}

// ---------------------------------------------------------------------------
// mma.sync GEMM: D = (Ah+Al)[M,K] @ B[N,K]^T + bias  (A fp16-split, B single fp16)
// BM=BN=128, BK=32, 8 warps (2x4), warp tile 64x32, cp.async double buffer.
// EPI=0: Q->split fp16 (scaled), K/V->single fp16, head-major. EPI=1: fp32 C.
// ---------------------------------------------------------------------------
#define TILE_B  10240           // 128 rows * 80B
#define STAGE_B 30720           // 3 tiles (Ah, Al, B)

template<int EPI>
__global__ __launch_bounds__(256, 2)
void mma_gemm(const __half* __restrict__ Ah, const __half* __restrict__ Al,
              const __half* __restrict__ Bs,
              const float* __restrict__ bias, float* __restrict__ C,
              int N, int K)
{
    extern __shared__ char dsm[];
    const uint32_t sb = smem_to_u32(dsm);

    const int tid = threadIdx.x;
    const int wid = tid >> 5;
    const int lane = tid & 31;
    const int bm = blockIdx.y;
    const int bn = blockIdx.x;
    const int wm = wid & 1;
    const int wn = wid >> 1;

    const __half* gsrc[3];
    gsrc[0] = Ah + (size_t)bm * 128 * K;
    gsrc[1] = Al + (size_t)bm * 128 * K;
    gsrc[2] = Bs + (size_t)bn * 128 * K;

    const int l_row0 = tid >> 2;
    const int l_c16  = tid & 3;

    auto load_stage = [&](int stage, int k0) {
        uint32_t sdst = sb + stage * STAGE_B;
        #pragma unroll
        for (int op = 0; op < 3; op++) {
            const __half* g = gsrc[op];
            #pragma unroll
            for (int h = 0; h < 2; h++) {
                int row = l_row0 + h * 64;
                cp_async16(sdst + op * TILE_B + row * 80 + l_c16 * 16,
                           g + (size_t)row * K + k0 + l_c16 * 8);
            }
        }
    };

    float acc[4][4][4];
    #pragma unroll
    for (int mt = 0; mt < 4; mt++)
        #pragma unroll
        for (int nt = 0; nt < 4; nt++)
            #pragma unroll
            for (int r = 0; r < 4; r++) acc[mt][nt][r] = 0.0f;

    const int NCH = K >> 5;

    load_stage(0, 0);
    CP_COMMIT();

    const uint32_t a_off = (uint32_t)(wm * 64 + (lane & 15)) * 80 + (uint32_t)(lane >> 4) * 16;
    const int bg = lane >> 3;
    const uint32_t b_off = (uint32_t)(wn * 32 + (lane & 7) + ((bg >> 1) << 3)) * 80
                         + (uint32_t)(bg & 1) * 16;

    for (int c = 0; c < NCH; c++) {
        const int stage = c & 1;
        if (c + 1 < NCH) {
            load_stage((c + 1) & 1, (c + 1) * 32);
            CP_COMMIT();
            CP_WAIT(1);
        } else {
            CP_WAIT(0);
        }
        __syncthreads();

        const uint32_t sA_h = sb + stage * STAGE_B + 0 * TILE_B;
        const uint32_t sA_l = sb + stage * STAGE_B + 1 * TILE_B;
        const uint32_t sB   = sb + stage * STAGE_B + 2 * TILE_B;

        #pragma unroll
        for (int ks = 0; ks < 2; ks++) {
            const uint32_t kbyte = ks * 32;
            uint32_t bf[2][4];
            #pragma unroll
            for (int nt2 = 0; nt2 < 2; nt2++)
                ldsm_x4(bf[nt2], sB + b_off + (uint32_t)nt2 * 16 * 80 + kbyte);
            #pragma unroll
            for (int mt = 0; mt < 4; mt++) {
                uint32_t ahf[4], alf[4];
                uint32_t roff = a_off + (uint32_t)mt * 16 * 80 + kbyte;
                ldsm_x4(ahf, sA_h + roff);
                ldsm_x4(alf, sA_l + roff);
                #pragma unroll
                for (int nt = 0; nt < 4; nt++)
                    mma_f16(acc[mt][nt], ahf, bf[nt >> 1][(nt & 1) * 2], bf[nt >> 1][(nt & 1) * 2 + 1]);
                #pragma unroll
                for (int nt = 0; nt < 4; nt++)
                    mma_f16(acc[mt][nt], alf, bf[nt >> 1][(nt & 1) * 2], bf[nt >> 1][(nt & 1) * 2 + 1]);
            }
        }
        __syncthreads();
    }

    #pragma unroll
    for (int mt = 0; mt < 4; mt++) {
        #pragma unroll
        for (int nt = 0; nt < 4; nt++) {
            #pragma unroll
            for (int r = 0; r < 4; r++) {
                int m = bm * 128 + wm * 64 + mt * 16 + (lane >> 2) + (r >> 1) * 8;
                int n = bn * 128 + wn * 32 + nt * 8 + (lane & 3) * 2 + (r & 1);
                float v = acc[mt][nt][r] + __ldg(&bias[n]);
                if (EPI == 0) {
                    int part = n >> 10;
                    int b = m >> 11;
                    int s = m & 2047;
                    int col = n & 1023;
                    int hh = col >> 6;
                    int d = col & 63;
                    size_t idx = (((size_t)(b * 16 + hh) * 2048) + s) * 64 + d;
                    if (part == 0) {
                        v *= 0.125f * LOG2E;      // scale + exp2-domain fold
                        __half hi = __float2half_rn(v);
                        g_qh[idx] = hi;
                        g_ql[idx] = __float2half_rn(v - __half2float(hi));
                    } else if (part == 1) {
                        g_k16[idx] = __float2half_rn(v);
                    } else {
                        g_v16[idx] = __float2half_rn(v);
                    }
                } else {
                    C[(size_t)m * N + n] = v;
                }
            }
        }
    }
}

// ---------------------------------------------------------------------------
// Tensor-core flash attention: Q fp16-split x K single; P fp16-split x V single.
// Bq=128, Bk=64, 8 warps (warp = 16 q-rows).
// smem: Qh/Ql 32KB + 2 stages x (K,V) 16KB = 64KB.
// ---------------------------------------------------------------------------
__global__ __launch_bounds__(256, 1)
void flash_mma()
{
    extern __shared__ char fsm[];
    const uint32_t sb = smem_to_u32(fsm);
    const uint32_t sQh = sb, sQl = sb + 16384;

    const int tid = threadIdx.x;
    const int lane = tid & 31;
    const int wid = tid >> 5;
    const int qt = 15 - blockIdx.x;       // heavy tiles first
    const int bh = blockIdx.y;

    const size_t qoff = ((size_t)bh * SS + qt * 128) * HD;

    auto load_Q = [&]() {
        #pragma unroll
        for (int i = 0; i < 4; i++) {
            int ch = tid + i * 256;
            int r = ch >> 3, c = ch & 7;
            cp_async16(sQh + SWZ(r, c), g_qh + qoff + (size_t)r * 64 + c * 8);
            cp_async16(sQl + SWZ(r, c), g_ql + qoff + (size_t)r * 64 + c * 8);
        }
    };
    auto load_KV = [&](int stage, int kt) {
        uint32_t sbase = sb + 32768 + stage * 16384;
        size_t off = ((size_t)bh * SS + kt * 64) * HD;
        const __half* srcs[2] = { g_k16 + off, g_v16 + off };
        #pragma unroll
        for (int b = 0; b < 2; b++)
            #pragma unroll
            for (int i = 0; i < 2; i++) {
                int ch = tid + i * 256;
                int r = ch >> 3, c = ch & 7;
                cp_async16(sbase + b * 8192 + SWZ(r, c), srcs[b] + (size_t)r * 64 + c * 8);
            }
    };

    const int nkt = 2 * qt + 2;

    load_Q();
    load_KV(0, 0);
    CP_COMMIT();

    uint32_t qh[4][4], ql[4][4];
    float oacc[8][4];
    #pragma unroll
    for (int nt = 0; nt < 8; nt++)
        #pragma unroll
        for (int j = 0; j < 4; j++) oacc[nt][j] = 0.0f;
    float m_s[2] = {-1e30f, -1e30f};
    float l_s[2] = {0.0f, 0.0f};

    for (int kt = 0; kt < nkt; kt++) {
        const int stage = kt & 1;
        if (kt + 1 < nkt) {
            load_KV((kt + 1) & 1, kt + 1);
            CP_COMMIT();
            CP_WAIT(1);
        } else {
            CP_WAIT(0);
        }
        __syncthreads();

        if (kt == 0) {
            #pragma unroll
            for (int t = 0; t < 4; t++) {
                int row = wid * 16 + (lane & 15);
                int c = t * 2 + (lane >> 4);
                ldsm_x4(qh[t], sQh + SWZ(row, c));
                ldsm_x4(ql[t], sQl + SWZ(row, c));
            }
        }

        const uint32_t stK = sb + 32768 + stage * 16384;
        const uint32_t stV = stK + 8192;

        float sacc[8][4];
        #pragma unroll
        for (int nt = 0; nt < 8; nt++)
            #pragma unroll
            for (int j = 0; j < 4; j++) sacc[nt][j] = 0.0f;

        // ---- S = (Qh+Ql) K^T (K single fp16) ----
        #pragma unroll
        for (int t = 0; t < 4; t++) {
            uint32_t k4[4][4];
            const int g = lane >> 3;
            #pragma unroll
            for (int p = 0; p < 4; p++) {
                int row = p * 16 + (lane & 7) + ((g >> 1) << 3);
                int c = t * 2 + (g & 1);
                ldsm_x4(k4[p], stK + SWZ(row, c));
            }
            #pragma unroll
            for (int p = 0; p < 4; p++) {
                mma_f16(sacc[2*p],   qh[t], k4[p][0], k4[p][1]);
                mma_f16(sacc[2*p+1], qh[t], k4[p][2], k4[p][3]);
            }
            #pragma unroll
            for (int p = 0; p < 4; p++) {
                mma_f16(sacc[2*p],   ql[t], k4[p][0], k4[p][1]);
                mma_f16(sacc[2*p+1], ql[t], k4[p][2], k4[p][3]);
            }
        }

        if (kt >= 2 * qt) {
            int r0 = qt * 128 + wid * 16 + (lane >> 2);
            #pragma unroll
            for (int nt = 0; nt < 8; nt++)
                #pragma unroll
                for (int j = 0; j < 4; j++) {
                    int row = r0 + (j >> 1) * 8;
                    int col = kt * 64 + nt * 8 + (lane & 3) * 2 + (j & 1);
                    if (col > row) sacc[nt][j] = -1e30f;
                }
        }

        float rmax[2] = {-1e30f, -1e30f};
        #pragma unroll
        for (int nt = 0; nt < 8; nt++) {
            rmax[0] = fmaxf(rmax[0], fmaxf(sacc[nt][0], sacc[nt][1]));
            rmax[1] = fmaxf(rmax[1], fmaxf(sacc[nt][2], sacc[nt][3]));
        }
        #pragma unroll
        for (int h = 0; h < 2; h++) {
            rmax[h] = fmaxf(rmax[h], __shfl_xor_sync(0xffffffffu, rmax[h], 1));
            rmax[h] = fmaxf(rmax[h], __shfl_xor_sync(0xffffffffu, rmax[h], 2));
        }
        float corr[2];
        #pragma unroll
        for (int h = 0; h < 2; h++) {
            float mnew = fmaxf(m_s[h], rmax[h]);
            corr[h] = fexp2(m_s[h] - mnew);
            m_s[h] = mnew;
        }

        uint32_t phpk[8][2], plpk[8][2];
        float rsum[2] = {0.0f, 0.0f};
        #pragma unroll
        for (int nt = 0; nt < 8; nt++) {
            #pragma unroll
            for (int h = 0; h < 2; h++) {
                float p0 = fexp2(sacc[nt][2*h]   - m_s[h]);
                float p1 = fexp2(sacc[nt][2*h+1] - m_s[h]);
                rsum[h] += p0 + p1;
                __half h0 = __float2half_rn(p0);
                __half h1 = __float2half_rn(p1);
                phpk[nt][h] = pack_f16(h0, h1);
                plpk[nt][h] = pack_f16(
                    __float2half_rn(p0 - __half2float(h0)),
                    __float2half_rn(p1 - __half2float(h1)));
            }
        }
        #pragma unroll
        for (int h = 0; h < 2; h++) {
            rsum[h] += __shfl_xor_sync(0xffffffffu, rsum[h], 1);
            rsum[h] += __shfl_xor_sync(0xffffffffu, rsum[h], 2);
            l_s[h] = l_s[h] * corr[h] + rsum[h];
        }
        #pragma unroll
        for (int nt = 0; nt < 8; nt++) {
            oacc[nt][0] *= corr[0];
            oacc[nt][1] *= corr[0];
            oacc[nt][2] *= corr[1];
            oacc[nt][3] *= corr[1];
        }

        // ---- O += (Ph+Pl) V (V single fp16) ----
        #pragma unroll
        for (int t = 0; t < 4; t++) {
            uint32_t pa_h[4] = { phpk[2*t][0], phpk[2*t][1], phpk[2*t+1][0], phpk[2*t+1][1] };
            uint32_t pa_l[4] = { plpk[2*t][0], plpk[2*t][1], plpk[2*t+1][0], plpk[2*t+1][1] };
            uint32_t v4[4][4];
            #pragma unroll
            for (int p = 0; p < 4; p++) {
                int row = t * 16 + (lane & 15);
                int c = 2 * p + (lane >> 4);
                ldsm_x4_t(v4[p], stV + SWZ(row, c));
            }
            #pragma unroll
            for (int p = 0; p < 4; p++) {
                mma_f16(oacc[2*p],   pa_h, v4[p][0], v4[p][1]);
                mma_f16(oacc[2*p+1], pa_h, v4[p][2], v4[p][3]);
            }
            #pragma unroll
            for (int p = 0; p < 4; p++) {
                mma_f16(oacc[2*p],   pa_l, v4[p][0], v4[p][1]);
                mma_f16(oacc[2*p+1], pa_l, v4[p][2], v4[p][3]);
            }
        }
        __syncthreads();
    }

    const int b = bh >> 4;
    const int head = bh & 15;
    float inv[2] = {1.0f / l_s[0], 1.0f / l_s[1]};
    #pragma unroll
    for (int h = 0; h < 2; h++) {
        int srow = qt * 128 + wid * 16 + (lane >> 2) + h * 8;
        size_t base = ((size_t)(b * SS + srow)) * DD + head * 64 + (lane & 3) * 2;
        #pragma unroll
        for (int nt = 0; nt < 8; nt++) {
            float o0 = oacc[nt][2*h]   * inv[h];
            float o1 = oacc[nt][2*h+1] * inv[h];
            __half h0 = __float2half_rn(o0);
            __half h1 = __float2half_rn(o1);
            *reinterpret_cast<uint32_t*>(g_ah + base + nt * 8) = pack_f16(h0, h1);
            *reinterpret_cast<uint32_t*>(g_al + base + nt * 8) = pack_f16(
                __float2half_rn(o0 - __half2float(h0)),
                __float2half_rn(o1 - __half2float(h1)));
        }
    }
}

// ---------------------------------------------------------------------------
extern "C" void kernel_launch(void* const* d_in, const int* in_sizes, int n_in,
                              void* d_out, int out_size)
{
    (void)in_sizes; (void)n_in; (void)out_size;
    const float* x   = (const float*)d_in[0];
    const float* w1  = (const float*)d_in[1];
    const float* b1  = (const float*)d_in[2];
    const float* w2  = (const float*)d_in[3];
    const float* b2  = (const float*)d_in[4];
    float* out = (float*)d_out;

    const int SMEM_DYN = 2 * STAGE_B;          // 61440
    const int SMEM_FL  = 65536;                // 64KB
    cudaFuncSetAttribute(mma_gemm<0>, cudaFuncAttributeMaxDynamicSharedMemorySize, SMEM_DYN);
    cudaFuncSetAttribute(mma_gemm<1>, cudaFuncAttributeMaxDynamicSharedMemorySize, SMEM_DYN);
    cudaFuncSetAttribute(flash_mma, cudaFuncAttributeMaxDynamicSharedMemorySize, SMEM_FL);

    void *p_xh, *p_xl, *p_w1t, *p_w2t, *p_ah, *p_al;
    cudaGetSymbolAddress(&p_xh, g_xh);   cudaGetSymbolAddress(&p_xl, g_xl);
    cudaGetSymbolAddress(&p_w1t, g_w1t); cudaGetSymbolAddress(&p_w2t, g_w2t);
    cudaGetSymbolAddress(&p_ah, g_ah);   cudaGetSymbolAddress(&p_al, g_al);

    split_kernel<<<MROWS * DD / 1024, 256>>>(x, (__half*)p_xh, (__half*)p_xl);
    tconv_kernel<<<dim3(3 * DD / 32, DD / 32), 256>>>(w1, (__half*)p_w1t, DD, 3 * DD);
    tconv_kernel<<<dim3(DD / 32, DD / 32), 256>>>(w2, (__half*)p_w2t, DD, DD);

    mma_gemm<0><<<dim3(3 * DD / 128, MROWS / 128), 256, SMEM_DYN>>>(
        (const __half*)p_xh, (const __half*)p_xl, (const __half*)p_w1t,
        b1, nullptr, 3 * DD, DD);

    flash_mma<<<dim3(SS / 128, BH), 256, SMEM_FL>>>();

    mma_gemm<1><<<dim3(DD / 128, MROWS / 128), 256, SMEM_DYN>>>(
        (const __half*)p_ah, (const __half*)p_al, (const __half*)p_w2t,
        b2, out, DD, DD);
}